// round 4
// baseline (speedup 1.0000x reference)
#include <cuda_runtime.h>

#define SQ 1024
#define BA 64
#define IN 256
#define HD 512
#define G4 2048

__device__ __align__(16) float g_WXt[IN * G4];
__device__ __align__(16) float g_BIAS[G4];
__device__ __align__(16) float g_WHg[G4 * HD];
__device__ __align__(16) float g_XG[(size_t)SQ * BA * G4];
__device__ __align__(16) float g_Hbuf[2][BA * HD];
__device__ unsigned g_cnt[4];

__global__ void prep_kernel(
    const float* Wxi, const float* bxi, const float* Whi, const float* bhi,
    const float* Wxf, const float* bxf, const float* Whf, const float* bhf,
    const float* Wxo, const float* bxo, const float* Who, const float* bho,
    const float* Wxc, const float* bxc, const float* Whc, const float* bhc)
{
    const float* Wx[4] = {Wxi, Wxf, Wxo, Wxc};
    const float* bx[4] = {bxi, bxf, bxo, bxc};
    const float* Wh[4] = {Whi, Whf, Who, Whc};
    const float* bh[4] = {bhi, bhf, bho, bhc};
    long idx = (long)blockIdx.x * 256 + threadIdx.x;

    if (idx < 524288L) {                       // WXt[i][n] = W_x{g}[j][i]
        int n = (int)(idx & 2047), i = (int)(idx >> 11);
        int g = n >> 9, j = n & 511;
        g_WXt[(size_t)i * G4 + n] = Wx[g][(size_t)j * IN + i];
        return;
    }
    idx -= 524288L;
    if (idx < 2048L) {                         // fused bias
        int g = (int)(idx >> 9), j = (int)(idx & 511);
        g_BIAS[idx] = bx[g][j] + bh[g][j];
        return;
    }
    idx -= 2048L;
    if (idx < 1048576L) {                      // WHg[hg][k][g*16+jl] = W_h{g}[hg*16+jl][k]
        int rr = (int)(idx & 63);
        int k  = (int)((idx >> 6) & 511);
        int hg = (int)(idx >> 15);
        int g = rr >> 4, j = hg * 16 + (rr & 15);
        g_WHg[idx] = Wh[g][(size_t)j * HD + k];
        return;
    }
    idx -= 1048576L;
    if (idx < 32768L) { g_Hbuf[1][idx] = 0.f; return; }
    idx -= 32768L;
    if (idx < 4L) g_cnt[idx] = 0u;
}

// ---- XG[s*64+b][n] = x[b][s][:] . WXt[:][n] + BIAS[n] ----
__global__ __launch_bounds__(256) void xproj_kernel(const float* __restrict__ x)
{
    __shared__ float As[32][128];
    __shared__ float Bs[32][128];
    int tid = threadIdx.x;
    int n0 = blockIdx.x * 128, m0 = blockIdx.y * 128;
    int tm = tid >> 4, tn = tid & 15;

    float acc[8][8];
#pragma unroll
    for (int i = 0; i < 8; i++)
#pragma unroll
        for (int j = 0; j < 8; j++) acc[i][j] = 0.f;

    int ra = tid >> 1;
    int khalf = (tid & 1) * 16;
    int m = m0 + ra;
    int xs = m >> 6, xb = m & 63;
    const float* xr = x + ((size_t)(xb * 1024 + xs)) * IN;
    int bkk = tid >> 3, bn = (tid & 7) * 4;

    for (int k0 = 0; k0 < IN; k0 += 32) {
#pragma unroll
        for (int u = 0; u < 4; u++) {
            float4 v = *(const float4*)(xr + k0 + khalf + u * 4);
            As[khalf + u * 4 + 0][ra] = v.x;
            As[khalf + u * 4 + 1][ra] = v.y;
            As[khalf + u * 4 + 2][ra] = v.z;
            As[khalf + u * 4 + 3][ra] = v.w;
        }
#pragma unroll
        for (int w = 0; w < 4; w++)
            *(float4*)&Bs[bkk][bn + w * 32] =
                *(const float4*)(g_WXt + (size_t)(k0 + bkk) * G4 + n0 + bn + w * 32);
        __syncthreads();
#pragma unroll
        for (int kk = 0; kk < 32; kk++) {
            float a[8], b[8];
            *(float4*)&a[0] = *(float4*)&As[kk][tm * 4];
            *(float4*)&a[4] = *(float4*)&As[kk][64 + tm * 4];
            *(float4*)&b[0] = *(float4*)&Bs[kk][tn * 4];
            *(float4*)&b[4] = *(float4*)&Bs[kk][64 + tn * 4];
#pragma unroll
            for (int i = 0; i < 8; i++)
#pragma unroll
                for (int j = 0; j < 8; j++)
                    acc[i][j] += a[i] * b[j];
        }
        __syncthreads();
    }
    float bias[8];
    *(float4*)&bias[0] = *(const float4*)(g_BIAS + n0 + tn * 4);
    *(float4*)&bias[4] = *(const float4*)(g_BIAS + n0 + 64 + tn * 4);
#pragma unroll
    for (int i = 0; i < 8; i++) {
        int r = (i < 4) ? (tm * 4 + i) : (64 + tm * 4 + (i - 4));
        float* orow = g_XG + (size_t)(m0 + r) * G4 + n0;
        *(float4*)(orow + tn * 4) = make_float4(acc[i][0] + bias[0], acc[i][1] + bias[1],
                                                acc[i][2] + bias[2], acc[i][3] + bias[3]);
        *(float4*)(orow + 64 + tn * 4) = make_float4(acc[i][4] + bias[4], acc[i][5] + bias[5],
                                                     acc[i][6] + bias[6], acc[i][7] + bias[7]);
    }
}

// ---- persistent recurrence: 128 CTAs = 4 batch-groups x 32 h-groups ----
#define SM_WS   (512 * 64)
#define SM_HS   (512 * 16)
#define SM_CRED (4 * 64 * 17)
#define SMEM_BYTES ((SM_WS + SM_HS + SM_CRED) * 4)

__global__ __launch_bounds__(256, 1) void lstm_kernel(float* __restrict__ out)
{
    extern __shared__ float smem[];
    float* Ws   = smem;
    float* Hs   = smem + SM_WS;
    float* Cred = smem + SM_WS + SM_HS;

    int tid = threadIdx.x;
    int bg = blockIdx.x >> 5;
    int hg = blockIdx.x & 31;

    {   // resident weights: 64 gate-rows of Wh, loaded once
        const float* src = g_WHg + (size_t)hg * SM_WS;
        for (int i = tid * 4; i < SM_WS; i += 256 * 4)
            *(float4*)&Ws[i] = *(const float4*)(src + i);
    }

    int kq = tid >> 6;
    int tt = tid & 63;
    int rg = tt >> 2, bq = tt & 3;
    int r0 = rg * 4, b0 = bq * 4;
    int n0 = (r0 >> 4) * HD + hg * 16 + (r0 & 15);

    int pb = tid >> 4, pj = tid & 15;
    int hb_off = (bg * 16 + pb) * HD + hg * 16 + pj;
    float c_reg = 0.f;

    int fb = tid & 15;
    int fk0 = (tid >> 4) * 32;

    __syncthreads();

    for (int s = 0; s < SQ; s++) {
        if (s > 0 && tid == 0) {
            // Bounded spin: if co-residency ever fails, fall through after the
            // fuse instead of hanging the GPU (wrong answer >> dead container).
            unsigned tgt = 32u * (unsigned)s;
            volatile unsigned* c = &g_cnt[bg];
            long fuse = 160000000L;
            while (*c < tgt && --fuse > 0) { __nanosleep(64); }
            __threadfence();
        }
        __syncthreads();

        float4 xgv[4];
        if (kq == 0) {
            const float* xgp = g_XG + ((size_t)(s * 64 + bg * 16 + b0)) * G4 + n0;
#pragma unroll
            for (int bi = 0; bi < 4; bi++)
                xgv[bi] = __ldg((const float4*)(xgp + (size_t)bi * G4));
        }

        {   // h_{s-1} -> Hs[k][b], L1-bypassed
            const float* hsrc = g_Hbuf[(s + 1) & 1] + (size_t)(bg * 16 + fb) * HD + fk0;
#pragma unroll
            for (int kk = 0; kk < 32; kk += 4) {
                float4 v = __ldcg((const float4*)(hsrc + kk));
                Hs[(fk0 + kk + 0) * 16 + fb] = v.x;
                Hs[(fk0 + kk + 1) * 16 + fb] = v.y;
                Hs[(fk0 + kk + 2) * 16 + fb] = v.z;
                Hs[(fk0 + kk + 3) * 16 + fb] = v.w;
            }
        }
        __syncthreads();

        float a00=0,a01=0,a02=0,a03=0,a10=0,a11=0,a12=0,a13=0;
        float a20=0,a21=0,a22=0,a23=0,a30=0,a31=0,a32=0,a33=0;
        {
            const float* wp = Ws + (size_t)(kq * 128) * 64 + r0;
            const float* hp = Hs + (size_t)(kq * 128) * 16 + b0;
#pragma unroll 4
            for (int k = 0; k < 128; k++) {
                float4 wv = *(const float4*)wp;
                float4 hv = *(const float4*)hp;
                a00 += wv.x*hv.x; a01 += wv.x*hv.y; a02 += wv.x*hv.z; a03 += wv.x*hv.w;
                a10 += wv.y*hv.x; a11 += wv.y*hv.y; a12 += wv.y*hv.z; a13 += wv.y*hv.w;
                a20 += wv.z*hv.x; a21 += wv.z*hv.y; a22 += wv.z*hv.z; a23 += wv.z*hv.w;
                a30 += wv.w*hv.x; a31 += wv.w*hv.y; a32 += wv.w*hv.z; a33 += wv.w*hv.w;
                wp += 64; hp += 16;
            }
        }
        {
            float* cp = Cred + (size_t)kq * 64 * 17;
            float a[4][4] = {{a00,a01,a02,a03},{a10,a11,a12,a13},
                             {a20,a21,a22,a23},{a30,a31,a32,a33}};
#pragma unroll
            for (int ri = 0; ri < 4; ri++)
#pragma unroll
                for (int bi = 0; bi < 4; bi++) {
                    float v = a[ri][bi];
                    if (kq == 0) v += ((const float*)&xgv[bi])[ri];
                    cp[(r0 + ri) * 17 + (b0 + bi)] = v;
                }
        }
        __syncthreads();

        {
            float gi = 0.f, gf = 0.f, go = 0.f, gc = 0.f;
#pragma unroll
            for (int q = 0; q < 4; q++) {
                const float* cp = Cred + (size_t)q * 64 * 17;
                gi += cp[(0 * 16 + pj) * 17 + pb];
                gf += cp[(1 * 16 + pj) * 17 + pb];
                go += cp[(2 * 16 + pj) * 17 + pb];
                gc += cp[(3 * 16 + pj) * 17 + pb];
            }
            float iv = 1.f / (1.f + __expf(-gi));
            float fv = 1.f / (1.f + __expf(-gf));
            float ov = 1.f / (1.f + __expf(-go));
            float gv = tanhf(gc);
            c_reg = fv * c_reg + iv * gv;
            float hv = ov * tanhf(c_reg);
            g_Hbuf[s & 1][hb_off] = hv;
            if (s == SQ - 1) {
                out[hb_off]         = hv;
                out[32768 + hb_off] = c_reg;
            }
        }
        __syncthreads();
        if (tid == 0) {
            __threadfence();
            atomicAdd(&g_cnt[bg], 1u);
        }
    }
}

extern "C" void kernel_launch(void* const* d_in, const int* in_sizes, int n_in,
                              void* d_out, int out_size)
{
    const float* x = (const float*)d_in[0];
    cudaFuncSetAttribute(lstm_kernel, cudaFuncAttributeMaxDynamicSharedMemorySize, SMEM_BYTES);

    prep_kernel<<<6281, 256>>>(
        (const float*)d_in[1],  (const float*)d_in[2],  (const float*)d_in[3],  (const float*)d_in[4],
        (const float*)d_in[5],  (const float*)d_in[6],  (const float*)d_in[7],  (const float*)d_in[8],
        (const float*)d_in[9],  (const float*)d_in[10], (const float*)d_in[11], (const float*)d_in[12],
        (const float*)d_in[13], (const float*)d_in[14], (const float*)d_in[15], (const float*)d_in[16]);

    dim3 g1(16, 512);
    xproj_kernel<<<g1, 256>>>(x);

    lstm_kernel<<<128, 256, SMEM_BYTES>>>((float*)d_out);
}

// round 6
// speedup vs baseline: 1.1460x; 1.1460x over previous
#include <cuda_runtime.h>
#include <cuda_bf16.h>
#include <cstdint>

#define SQ 1024
#define BA 64
#define IN 256
#define HD 512
#define G4 2048
#define WPAD 520   // padded k-stride (bf16 elems) for conflict-free ldmatrix

// ---------------- device scratch ----------------
__device__ __align__(16) float g_WXt[IN * G4];
__device__ __align__(16) float g_BIAS[G4];
__device__ __align__(16) __nv_bfloat16 g_WHhi[32 * 64 * 512];  // [hg][row=g*16+jl][k]
__device__ __align__(16) __nv_bfloat16 g_WHlo[32 * 64 * 512];
__device__ __align__(16) float g_XG[(size_t)SQ * BA * G4];
__device__ __align__(16) __nv_bfloat16 g_Hhi[2][BA * HD];      // [b][j]
__device__ __align__(16) __nv_bfloat16 g_Hlo[2][BA * HD];
__device__ unsigned g_cnt[4];

// ---------------- warp MMA helpers (sm_80+ baseline, works on sm_100) ----------------
__device__ __forceinline__ uint32_t smem_u32(const void* p) {
    uint32_t a;
    asm("{ .reg .u64 t; cvta.to.shared.u64 t, %1; cvt.u32.u64 %0, t; }" : "=r"(a) : "l"(p));
    return a;
}
__device__ __forceinline__ void ldsm4(uint32_t* r, uint32_t a) {
    asm volatile("ldmatrix.sync.aligned.m8n8.x4.shared.b16 {%0,%1,%2,%3}, [%4];"
                 : "=r"(r[0]), "=r"(r[1]), "=r"(r[2]), "=r"(r[3]) : "r"(a));
}
__device__ __forceinline__ void ldsm2(uint32_t* r, uint32_t a) {
    asm volatile("ldmatrix.sync.aligned.m8n8.x2.shared.b16 {%0,%1}, [%2];"
                 : "=r"(r[0]), "=r"(r[1]) : "r"(a));
}
__device__ __forceinline__ void mma16816(float& d0, float& d1, float& d2, float& d3,
                                         const uint32_t* a, const uint32_t* b) {
    asm volatile("mma.sync.aligned.m16n8k16.row.col.f32.bf16.bf16.f32 "
                 "{%0,%1,%2,%3}, {%4,%5,%6,%7}, {%8,%9}, {%0,%1,%2,%3};"
                 : "+f"(d0), "+f"(d1), "+f"(d2), "+f"(d3)
                 : "r"(a[0]), "r"(a[1]), "r"(a[2]), "r"(a[3]), "r"(b[0]), "r"(b[1]));
}

// ---------------- prep ----------------
__global__ void prep_kernel(
    const float* Wxi, const float* bxi, const float* Whi, const float* bhi,
    const float* Wxf, const float* bxf, const float* Whf, const float* bhf,
    const float* Wxo, const float* bxo, const float* Who, const float* bho,
    const float* Wxc, const float* bxc, const float* Whc, const float* bhc)
{
    const float* Wx[4] = {Wxi, Wxf, Wxo, Wxc};
    const float* bx[4] = {bxi, bxf, bxo, bxc};
    const float* Wh[4] = {Whi, Whf, Who, Whc};
    const float* bh[4] = {bhi, bhf, bho, bhc};
    long idx = (long)blockIdx.x * 256 + threadIdx.x;

    if (idx < 524288L) {                       // WXt[i][n] = W_x{g}[j][i]
        int n = (int)(idx & 2047), i = (int)(idx >> 11);
        int g = n >> 9, j = n & 511;
        g_WXt[(size_t)i * G4 + n] = Wx[g][(size_t)j * IN + i];
        return;
    }
    idx -= 524288L;
    if (idx < 2048L) {
        int g = (int)(idx >> 9), j = (int)(idx & 511);
        g_BIAS[idx] = bx[g][j] + bh[g][j];
        return;
    }
    idx -= 2048L;
    if (idx < 1048576L) {                      // WHhi/lo[hg][r=g*16+jl][k] = split(W_h{g}[hg*16+jl][k])
        int k = (int)(idx & 511);
        int r = (int)((idx >> 9) & 63);
        int hg = (int)(idx >> 15);
        int g = r >> 4, j = hg * 16 + (r & 15);
        float w = Wh[g][(size_t)j * HD + k];
        __nv_bfloat16 hi = __float2bfloat16(w);
        g_WHhi[idx] = hi;
        g_WHlo[idx] = __float2bfloat16(w - __bfloat162float(hi));
        return;
    }
    idx -= 1048576L;
    if (idx < 32768L) {
        __nv_bfloat16 z = __float2bfloat16(0.f);
        g_Hhi[1][idx] = z;
        g_Hlo[1][idx] = z;
        return;
    }
    idx -= 32768L;
    if (idx < 4L) g_cnt[idx] = 0u;
}

// ---------------- xproj (unchanged, proven) ----------------
__global__ __launch_bounds__(256) void xproj_kernel(const float* __restrict__ x)
{
    __shared__ float As[32][128];
    __shared__ float Bs[32][128];
    int tid = threadIdx.x;
    int n0 = blockIdx.x * 128, m0 = blockIdx.y * 128;
    int tm = tid >> 4, tn = tid & 15;

    float acc[8][8];
#pragma unroll
    for (int i = 0; i < 8; i++)
#pragma unroll
        for (int j = 0; j < 8; j++) acc[i][j] = 0.f;

    int ra = tid >> 1;
    int khalf = (tid & 1) * 16;
    int m = m0 + ra;
    int xs = m >> 6, xb = m & 63;
    const float* xr = x + ((size_t)(xb * 1024 + xs)) * IN;
    int bkk = tid >> 3, bn = (tid & 7) * 4;

    for (int k0 = 0; k0 < IN; k0 += 32) {
#pragma unroll
        for (int u = 0; u < 4; u++) {
            float4 v = *(const float4*)(xr + k0 + khalf + u * 4);
            As[khalf + u * 4 + 0][ra] = v.x;
            As[khalf + u * 4 + 1][ra] = v.y;
            As[khalf + u * 4 + 2][ra] = v.z;
            As[khalf + u * 4 + 3][ra] = v.w;
        }
#pragma unroll
        for (int w = 0; w < 4; w++)
            *(float4*)&Bs[bkk][bn + w * 32] =
                *(const float4*)(g_WXt + (size_t)(k0 + bkk) * G4 + n0 + bn + w * 32);
        __syncthreads();
#pragma unroll
        for (int kk = 0; kk < 32; kk++) {
            float a[8], b[8];
            *(float4*)&a[0] = *(float4*)&As[kk][tm * 4];
            *(float4*)&a[4] = *(float4*)&As[kk][64 + tm * 4];
            *(float4*)&b[0] = *(float4*)&Bs[kk][tn * 4];
            *(float4*)&b[4] = *(float4*)&Bs[kk][64 + tn * 4];
#pragma unroll
            for (int i = 0; i < 8; i++)
#pragma unroll
                for (int j = 0; j < 8; j++)
                    acc[i][j] += a[i] * b[j];
        }
        __syncthreads();
    }
    float bias[8];
    *(float4*)&bias[0] = *(const float4*)(g_BIAS + n0 + tn * 4);
    *(float4*)&bias[4] = *(const float4*)(g_BIAS + n0 + 64 + tn * 4);
#pragma unroll
    for (int i = 0; i < 8; i++) {
        int r = (i < 4) ? (tm * 4 + i) : (64 + tm * 4 + (i - 4));
        float* orow = g_XG + (size_t)(m0 + r) * G4 + n0;
        *(float4*)(orow + tn * 4) = make_float4(acc[i][0] + bias[0], acc[i][1] + bias[1],
                                                acc[i][2] + bias[2], acc[i][3] + bias[3]);
        *(float4*)(orow + 64 + tn * 4) = make_float4(acc[i][4] + bias[4], acc[i][5] + bias[5],
                                                     acc[i][6] + bias[6], acc[i][7] + bias[7]);
    }
}

// ---------------- lstm: persistent HMMA recurrence ----------------
// 128 CTAs = 4 batch-groups x 32 h-groups. Per CTA: M=64 gate rows, N=16 batches, K=512.
// D = Whi*hhi + Whi*hlo + Wlo*hhi via mma.sync bf16, fp32 accum.
#define OFF_WHI  0
#define OFF_WLO  (64 * WPAD * 2)                 // 66560
#define OFF_HHI  (OFF_WLO + 64 * WPAD * 2)       // 133120
#define OFF_HLO  (OFF_HHI + 16 * WPAD * 2)       // 149760
#define OFF_CRED (OFF_HLO + 16 * WPAD * 2)       // 166400
#define LSMEM_BYTES (OFF_CRED + 64 * 17 * 4)     // 170752

__global__ __launch_bounds__(256, 1) void lstm_hmma_kernel(float* __restrict__ out)
{
    extern __shared__ char sm[];
    int tid = threadIdx.x;
    int wid = tid >> 5, lane = tid & 31;
    int bg = blockIdx.x >> 5;
    int hg = blockIdx.x & 31;
    int mw = wid & 3, nh = wid >> 2;

    {   // resident weights (once): [64][512] -> [64][WPAD] bf16, hi & lo
        int r = tid >> 2, part = tid & 3;
        const uint4* shi = (const uint4*)(g_WHhi + ((size_t)(hg * 64 + r) << 9) + part * 128);
        const uint4* slo = (const uint4*)(g_WHlo + ((size_t)(hg * 64 + r) << 9) + part * 128);
        uint4* dhi = (uint4*)(sm + OFF_WHI + (r * WPAD + part * 128) * 2);
        uint4* dlo = (uint4*)(sm + OFF_WLO + (r * WPAD + part * 128) * 2);
#pragma unroll
        for (int i = 0; i < 16; i++) { dhi[i] = shi[i]; dlo[i] = slo[i]; }
    }

    uint32_t smb = smem_u32(sm);
    // ldmatrix lane bases (A: x4 over 16x16; B: x2 over n8 x k16)
    int arow = lane & 15, akoff = (lane >= 16) ? 8 : 0;
    uint32_t aHiB = smb + OFF_WHI + ((mw * 16 + arow) * WPAD + akoff) * 2;
    uint32_t aLoB = smb + OFF_WLO + ((mw * 16 + arow) * WPAD + akoff) * 2;
    int brow = lane & 7, bkoff = (lane & 8) ? 8 : 0;
    uint32_t bHiB = smb + OFF_HHI + ((nh * 8 + brow) * WPAD + bkoff) * 2;
    uint32_t bLoB = smb + OFF_HLO + ((nh * 8 + brow) * WPAD + bkoff) * 2;

    float* Cred = (float*)(sm + OFF_CRED);
    int drow = mw * 16 + (lane >> 2), dcol = nh * 8 + (lane & 3) * 2;

    // pointwise cell: one (jl, b) per thread
    int jl = tid & 15, b = tid >> 4;
    int hwr = (bg * 16 + b) * HD + hg * 16 + jl;
    float c_reg = 0.f;

    __syncthreads();

    for (int s = 0; s < SQ; s++) {
        if (s > 0 && tid == 0) {
            unsigned tgt = 32u * (unsigned)s;
            volatile unsigned* c = &g_cnt[bg];
            long fuse = 160000000L;
            while (*c < tgt && --fuse > 0) __nanosleep(32);
            __threadfence();
        }
        __syncthreads();

        {   // h_{s-1} bf16 hi/lo -> SMEM [16][WPAD] (no transpose; L1-bypassed)
            int t = tid & 127;
            int row = t >> 3, ch = (t & 7) * 64;
            const __nv_bfloat16* hb = (tid < 128) ? g_Hhi[(s + 1) & 1] : g_Hlo[(s + 1) & 1];
            const uint4* srcv = (const uint4*)(hb + (size_t)(bg * 16 + row) * HD + ch);
            uint4* dst = (uint4*)(sm + ((tid < 128) ? OFF_HHI : OFF_HLO) + (row * WPAD + ch) * 2);
#pragma unroll
            for (int c = 0; c < 8; c++) dst[c] = __ldcg(srcv + c);
        }
        __syncthreads();

        float d0 = 0.f, d1 = 0.f, d2 = 0.f, d3 = 0.f;
#pragma unroll 4
        for (int ks = 0; ks < 32; ks++) {
            uint32_t ko = (uint32_t)ks * 32;   // 16 bf16 = 32 bytes
            uint32_t ahi[4], alo[4], bhi[2], blo[2];
            ldsm4(ahi, aHiB + ko);
            ldsm2(bhi, bHiB + ko);
            ldsm2(blo, bLoB + ko);
            ldsm4(alo, aLoB + ko);
            mma16816(d0, d1, d2, d3, ahi, bhi);
            mma16816(d0, d1, d2, d3, ahi, blo);
            mma16816(d0, d1, d2, d3, alo, bhi);
        }
        Cred[drow * 17 + dcol]           = d0;
        Cred[drow * 17 + dcol + 1]       = d1;
        Cred[(drow + 8) * 17 + dcol]     = d2;
        Cred[(drow + 8) * 17 + dcol + 1] = d3;
        __syncthreads();

        {   // pointwise
            const float* xgr = g_XG + (((size_t)(s * 64 + bg * 16 + b)) << 11) + hg * 16 + jl;
            float gi = Cred[jl * 17 + b]        + __ldg(xgr);
            float gf = Cred[(16 + jl) * 17 + b] + __ldg(xgr + 512);
            float go = Cred[(32 + jl) * 17 + b] + __ldg(xgr + 1024);
            float gc = Cred[(48 + jl) * 17 + b] + __ldg(xgr + 1536);
            float iv = 1.f / (1.f + __expf(-gi));
            float fv = 1.f / (1.f + __expf(-gf));
            float ov = 1.f / (1.f + __expf(-go));
            float gv = tanhf(gc);
            c_reg = fv * c_reg + iv * gv;
            float hv = ov * tanhf(c_reg);
            __nv_bfloat16 hi = __float2bfloat16(hv);
            g_Hhi[s & 1][hwr] = hi;
            g_Hlo[s & 1][hwr] = __float2bfloat16(hv - __bfloat162float(hi));
            if (s == SQ - 1) {
                out[hwr]         = hv;
                out[32768 + hwr] = c_reg;
            }
        }
        __threadfence();
        __syncthreads();
        if (tid == 0) atomicAdd(&g_cnt[bg], 1u);
    }
}

// ---------------- launch ----------------
extern "C" void kernel_launch(void* const* d_in, const int* in_sizes, int n_in,
                              void* d_out, int out_size)
{
    const float* x = (const float*)d_in[0];
    cudaFuncSetAttribute(lstm_hmma_kernel, cudaFuncAttributeMaxDynamicSharedMemorySize, LSMEM_BYTES);

    prep_kernel<<<6281, 256>>>(
        (const float*)d_in[1],  (const float*)d_in[2],  (const float*)d_in[3],  (const float*)d_in[4],
        (const float*)d_in[5],  (const float*)d_in[6],  (const float*)d_in[7],  (const float*)d_in[8],
        (const float*)d_in[9],  (const float*)d_in[10], (const float*)d_in[11], (const float*)d_in[12],
        (const float*)d_in[13], (const float*)d_in[14], (const float*)d_in[15], (const float*)d_in[16]);

    dim3 g1(16, 512);
    xproj_kernel<<<g1, 256>>>(x);

    lstm_hmma_kernel<<<128, 256, LSMEM_BYTES>>>((float*)d_out);
}

// round 7
// speedup vs baseline: 1.3920x; 1.2147x over previous
#include <cuda_runtime.h>
#include <cuda_bf16.h>
#include <cstdint>
#include <cstring>

#define SQ 1024
#define BA 64
#define IN 256
#define HD 512
#define G4 2048
#define WPAD 520

// ---------------- device scratch ----------------
__device__ __align__(16) float g_BIAS[G4];
__device__ __align__(16) __nv_bfloat16 g_WXhi[G4 * IN];        // [n][i] natural
__device__ __align__(16) __nv_bfloat16 g_WXlo[G4 * IN];
__device__ __align__(16) __nv_bfloat16 g_Xhi[(size_t)65536 * IN];  // [m=(s<<6)|b][i]
__device__ __align__(16) __nv_bfloat16 g_Xlo[(size_t)65536 * IN];
__device__ __align__(16) __nv_bfloat16 g_WHhi[32 * 64 * 512];  // [hg][row=g*16+jl][k]
__device__ __align__(16) __nv_bfloat16 g_WHlo[32 * 64 * 512];
__device__ __align__(16) float g_XG[(size_t)SQ * BA * G4];
__device__ __align__(16) __nv_bfloat16 g_Hhi[2][BA * HD];
__device__ __align__(16) __nv_bfloat16 g_Hlo[2][BA * HD];
__device__ unsigned g_cnt[4];

// ---------------- helpers ----------------
__device__ __forceinline__ uint32_t smem_u32(const void* p) {
    uint32_t a;
    asm("{ .reg .u64 t; cvta.to.shared.u64 t, %1; cvt.u32.u64 %0, t; }" : "=r"(a) : "l"(p));
    return a;
}
__device__ __forceinline__ void ldsm4(uint32_t* r, uint32_t a) {
    asm volatile("ldmatrix.sync.aligned.m8n8.x4.shared.b16 {%0,%1,%2,%3}, [%4];"
                 : "=r"(r[0]), "=r"(r[1]), "=r"(r[2]), "=r"(r[3]) : "r"(a));
}
__device__ __forceinline__ void ldsm2(uint32_t* r, uint32_t a) {
    asm volatile("ldmatrix.sync.aligned.m8n8.x2.shared.b16 {%0,%1}, [%2];"
                 : "=r"(r[0]), "=r"(r[1]) : "r"(a));
}
__device__ __forceinline__ void mma16816(float* d, const uint32_t* a, const uint32_t* b) {
    asm volatile("mma.sync.aligned.m16n8k16.row.col.f32.bf16.bf16.f32 "
                 "{%0,%1,%2,%3}, {%4,%5,%6,%7}, {%8,%9}, {%0,%1,%2,%3};"
                 : "+f"(d[0]), "+f"(d[1]), "+f"(d[2]), "+f"(d[3])
                 : "r"(a[0]), "r"(a[1]), "r"(a[2]), "r"(a[3]), "r"(b[0]), "r"(b[1]));
}
__device__ __forceinline__ void st_cg_u16(__nv_bfloat16* p, __nv_bfloat16 v) {
    unsigned short us;
    memcpy(&us, &v, 2);
    asm volatile("st.global.cg.u16 [%0], %1;" :: "l"(p), "h"(us) : "memory");
}

// ---------------- prep ----------------
__global__ void prep_kernel(
    const float* Wxi, const float* bxi, const float* Whi, const float* bhi,
    const float* Wxf, const float* bxf, const float* Whf, const float* bhf,
    const float* Wxo, const float* bxo, const float* Who, const float* bho,
    const float* Wxc, const float* bxc, const float* Whc, const float* bhc)
{
    const float* Wx[4] = {Wxi, Wxf, Wxo, Wxc};
    const float* bx[4] = {bxi, bxf, bxo, bxc};
    const float* Wh[4] = {Whi, Whf, Who, Whc};
    const float* bh[4] = {bhi, bhf, bho, bhc};
    long idx = (long)blockIdx.x * 256 + threadIdx.x;

    if (idx < 524288L) {                       // WX split, natural [n][i]
        int i = (int)(idx & 255), n = (int)(idx >> 8);
        int g = n >> 9, j = n & 511;
        float w = Wx[g][(size_t)j * IN + i];
        __nv_bfloat16 hi = __float2bfloat16(w);
        g_WXhi[idx] = hi;
        g_WXlo[idx] = __float2bfloat16(w - __bfloat162float(hi));
        return;
    }
    idx -= 524288L;
    if (idx < 2048L) {
        int g = (int)(idx >> 9), j = (int)(idx & 511);
        g_BIAS[idx] = bx[g][j] + bh[g][j];
        return;
    }
    idx -= 2048L;
    if (idx < 1048576L) {                      // WH split
        int k = (int)(idx & 511);
        int r = (int)((idx >> 9) & 63);
        int hg = (int)(idx >> 15);
        int g = r >> 4, j = hg * 16 + (r & 15);
        float w = Wh[g][(size_t)j * HD + k];
        __nv_bfloat16 hi = __float2bfloat16(w);
        g_WHhi[idx] = hi;
        g_WHlo[idx] = __float2bfloat16(w - __bfloat162float(hi));
        return;
    }
    idx -= 1048576L;
    if (idx < 32768L) {
        __nv_bfloat16 z = __float2bfloat16(0.f);
        g_Hhi[1][idx] = z;
        g_Hlo[1][idx] = z;
        return;
    }
    idx -= 32768L;
    if (idx < 4L) g_cnt[idx] = 0u;
}

// ---------------- x split: x[b][s][i] -> g_Xhi/lo[(s<<6)|b][i] ----------------
__global__ __launch_bounds__(256) void xsplit_kernel(const float* __restrict__ x)
{
    long idx = (long)blockIdx.x * 256 + threadIdx.x;   // float4 index
    long e = idx * 4;
    int i = (int)(e & 255);
    int s = (int)((e >> 8) & 1023);
    int b = (int)(e >> 18);
    float4 v = __ldg((const float4*)(x + e));
    float vv[4] = {v.x, v.y, v.z, v.w};
    __nv_bfloat16 h[4], l[4];
#pragma unroll
    for (int t = 0; t < 4; t++) {
        h[t] = __float2bfloat16(vv[t]);
        l[t] = __float2bfloat16(vv[t] - __bfloat162float(h[t]));
    }
    size_t off = (((size_t)((s << 6) | b)) << 8) + i;
    *(uint2*)(g_Xhi + off) = *(uint2*)h;
    *(uint2*)(g_Xlo + off) = *(uint2*)l;
}

// ---------------- xproj: HMMA, XG = x @ Wx^T + bias (3-term split) ----------------
#define XPAD 136
#define XS_AH 0
#define XS_AL (128 * XPAD * 2)
#define XS_BH (2 * 128 * XPAD * 2)
#define XS_BL (3 * 128 * XPAD * 2)
#define XSMEM_BYTES (4 * 128 * XPAD * 2)

__global__ __launch_bounds__(256, 1) void xproj_hmma_kernel()
{
    extern __shared__ char sm[];
    int tid = threadIdx.x;
    int wid = tid >> 5, lane = tid & 31;
    int n0 = blockIdx.x * 128, m0 = blockIdx.y * 128;
    int mh = wid & 1, nh = wid >> 1;     // warp tile: M=64, N=32

    uint32_t smb = smem_u32(sm);
    int arow = lane & 15, ak = (lane >= 16) ? 8 : 0;
    uint32_t aBH = smb + XS_AH + ((mh * 64 + arow) * XPAD + ak) * 2;
    uint32_t aBL = smb + XS_AL + ((mh * 64 + arow) * XPAD + ak) * 2;
    int brow = lane & 7, bk = (lane & 8) ? 8 : 0;
    uint32_t bBH = smb + XS_BH + ((nh * 32 + brow) * XPAD + bk) * 2;
    uint32_t bBL = smb + XS_BL + ((nh * 32 + brow) * XPAD + bk) * 2;

    float d[4][4][4];
#pragma unroll
    for (int mi = 0; mi < 4; mi++)
#pragma unroll
        for (int ni = 0; ni < 4; ni++)
#pragma unroll
            for (int q = 0; q < 4; q++) d[mi][ni][q] = 0.f;

    int fr = tid >> 1, fh = (tid & 1) * 64;
#pragma unroll
    for (int kc = 0; kc < 2; kc++) {
        int k0 = kc * 128;
        {   // fill A (x) and B (Wx) hi/lo tiles
            const uint4* sah = (const uint4*)(g_Xhi + (((size_t)(m0 + fr)) << 8) + k0 + fh);
            const uint4* sal = (const uint4*)(g_Xlo + (((size_t)(m0 + fr)) << 8) + k0 + fh);
            const uint4* sbh = (const uint4*)(g_WXhi + (((size_t)(n0 + fr)) << 8) + k0 + fh);
            const uint4* sbl = (const uint4*)(g_WXlo + (((size_t)(n0 + fr)) << 8) + k0 + fh);
            uint4* dah = (uint4*)(sm + XS_AH + (fr * XPAD + fh) * 2);
            uint4* dal = (uint4*)(sm + XS_AL + (fr * XPAD + fh) * 2);
            uint4* dbh = (uint4*)(sm + XS_BH + (fr * XPAD + fh) * 2);
            uint4* dbl = (uint4*)(sm + XS_BL + (fr * XPAD + fh) * 2);
#pragma unroll
            for (int c = 0; c < 8; c++) {
                dah[c] = __ldg(sah + c);
                dal[c] = __ldg(sal + c);
                dbh[c] = __ldg(sbh + c);
                dbl[c] = __ldg(sbl + c);
            }
        }
        __syncthreads();
#pragma unroll
        for (int ks = 0; ks < 8; ks++) {
            uint32_t ko = (uint32_t)ks * 32;
            uint32_t ah[4][4], al[4][4], bh[4][2], bl[4][2];
#pragma unroll
            for (int mi = 0; mi < 4; mi++) {
                ldsm4(ah[mi], aBH + mi * (16 * XPAD * 2) + ko);
                ldsm4(al[mi], aBL + mi * (16 * XPAD * 2) + ko);
            }
#pragma unroll
            for (int ni = 0; ni < 4; ni++) {
                ldsm2(bh[ni], bBH + ni * (8 * XPAD * 2) + ko);
                ldsm2(bl[ni], bBL + ni * (8 * XPAD * 2) + ko);
            }
#pragma unroll
            for (int mi = 0; mi < 4; mi++)
#pragma unroll
                for (int ni = 0; ni < 4; ni++) {
                    mma16816(d[mi][ni], ah[mi], bh[ni]);
                    mma16816(d[mi][ni], ah[mi], bl[ni]);
                    mma16816(d[mi][ni], al[mi], bh[ni]);
                }
        }
        __syncthreads();
    }

    int row_l = lane >> 2, col_l = (lane & 3) * 2;
#pragma unroll
    for (int mi = 0; mi < 4; mi++)
#pragma unroll
        for (int ni = 0; ni < 4; ni++) {
            int gr = m0 + mh * 64 + mi * 16 + row_l;
            int gc = n0 + nh * 32 + ni * 8 + col_l;
            float2 bb = *(const float2*)(g_BIAS + gc);
            float* o = g_XG + (size_t)gr * G4 + gc;
            *(float2*)o = make_float2(d[mi][ni][0] + bb.x, d[mi][ni][1] + bb.y);
            *(float2*)(o + 8 * G4) = make_float2(d[mi][ni][2] + bb.x, d[mi][ni][3] + bb.y);
        }
}

// ---------------- lstm: persistent HMMA recurrence ----------------
#define OFF_WHI  0
#define OFF_WLO  (64 * WPAD * 2)
#define OFF_HHI  (OFF_WLO + 64 * WPAD * 2)
#define OFF_HLO  (OFF_HHI + 16 * WPAD * 2)
#define OFF_CRED (OFF_HLO + 16 * WPAD * 2)
#define LSMEM_BYTES (OFF_CRED + 64 * 17 * 4)

__global__ __launch_bounds__(256, 1) void lstm_hmma_kernel(float* __restrict__ out)
{
    extern __shared__ char sm[];
    int tid = threadIdx.x;
    int wid = tid >> 5, lane = tid & 31;
    int bg = blockIdx.x >> 5;
    int hg = blockIdx.x & 31;
    int mw = wid & 3, nh = wid >> 2;

    {   // resident weights
        int r = tid >> 2, part = tid & 3;
        const uint4* shi = (const uint4*)(g_WHhi + ((size_t)(hg * 64 + r) << 9) + part * 128);
        const uint4* slo = (const uint4*)(g_WHlo + ((size_t)(hg * 64 + r) << 9) + part * 128);
        uint4* dhi = (uint4*)(sm + OFF_WHI + (r * WPAD + part * 128) * 2);
        uint4* dlo = (uint4*)(sm + OFF_WLO + (r * WPAD + part * 128) * 2);
#pragma unroll
        for (int i = 0; i < 16; i++) { dhi[i] = shi[i]; dlo[i] = slo[i]; }
    }

    uint32_t smb = smem_u32(sm);
    int arow = lane & 15, akoff = (lane >= 16) ? 8 : 0;
    uint32_t aHiB = smb + OFF_WHI + ((mw * 16 + arow) * WPAD + akoff) * 2;
    uint32_t aLoB = smb + OFF_WLO + ((mw * 16 + arow) * WPAD + akoff) * 2;
    int brow = lane & 7, bkoff = (lane & 8) ? 8 : 0;
    uint32_t bHiB = smb + OFF_HHI + ((nh * 8 + brow) * WPAD + bkoff) * 2;
    uint32_t bLoB = smb + OFF_HLO + ((nh * 8 + brow) * WPAD + bkoff) * 2;

    float* Cred = (float*)(sm + OFF_CRED);
    int drow = mw * 16 + (lane >> 2), dcol = nh * 8 + (lane & 3) * 2;

    int jl = tid & 15, b = tid >> 4;
    int hwr = (bg * 16 + b) * HD + hg * 16 + jl;
    float c_reg = 0.f;

    __syncthreads();

    for (int s = 0; s < SQ; s++) {
        // prefetch xg (independent of barrier -> latency hidden behind spin)
        float xgi, xgf, xgo, xgc;
        {
            const float* xgr = g_XG + (((size_t)(s * 64 + bg * 16 + b)) << 11) + hg * 16 + jl;
            xgi = __ldg(xgr);
            xgf = __ldg(xgr + 512);
            xgo = __ldg(xgr + 1024);
            xgc = __ldg(xgr + 1536);
        }
        if (s > 0 && tid == 0) {
            unsigned tgt = 32u * (unsigned)s;
            long fuse = 400000000L;
            unsigned v;
            do {
                asm volatile("ld.acquire.gpu.global.u32 %0, [%1];"
                             : "=r"(v) : "l"(&g_cnt[bg]) : "memory");
            } while (v < tgt && --fuse > 0);
        }
        __syncthreads();

        {   // h_{s-1} bf16 hi/lo -> SMEM [16][WPAD]
            int t = tid & 127;
            int row = t >> 3, ch = (t & 7) * 64;
            const __nv_bfloat16* hb = (tid < 128) ? g_Hhi[(s + 1) & 1] : g_Hlo[(s + 1) & 1];
            const uint4* srcv = (const uint4*)(hb + (size_t)(bg * 16 + row) * HD + ch);
            uint4* dst = (uint4*)(sm + ((tid < 128) ? OFF_HHI : OFF_HLO) + (row * WPAD + ch) * 2);
#pragma unroll
            for (int c = 0; c < 8; c++) dst[c] = __ldcg(srcv + c);
        }
        __syncthreads();

        float dd[4] = {0.f, 0.f, 0.f, 0.f};
#pragma unroll 4
        for (int ks = 0; ks < 32; ks++) {
            uint32_t ko = (uint32_t)ks * 32;
            uint32_t ahi[4], alo[4], bhi[2], blo[2];
            ldsm4(ahi, aHiB + ko);
            ldsm2(bhi, bHiB + ko);
            ldsm2(blo, bLoB + ko);
            ldsm4(alo, aLoB + ko);
            mma16816(dd, ahi, bhi);
            mma16816(dd, ahi, blo);
            mma16816(dd, alo, bhi);
        }
        Cred[drow * 17 + dcol]           = dd[0];
        Cred[drow * 17 + dcol + 1]       = dd[1];
        Cred[(drow + 8) * 17 + dcol]     = dd[2];
        Cred[(drow + 8) * 17 + dcol + 1] = dd[3];
        __syncthreads();

        {   // pointwise with prefetched xg
            float gi = Cred[jl * 17 + b]        + xgi;
            float gf = Cred[(16 + jl) * 17 + b] + xgf;
            float go = Cred[(32 + jl) * 17 + b] + xgo;
            float gc = Cred[(48 + jl) * 17 + b] + xgc;
            float iv = 1.f / (1.f + __expf(-gi));
            float fv = 1.f / (1.f + __expf(-gf));
            float ov = 1.f / (1.f + __expf(-go));
            float gv = tanhf(gc);
            c_reg = fv * c_reg + iv * gv;
            float hv = ov * tanhf(c_reg);
            __nv_bfloat16 hi = __float2bfloat16(hv);
            __nv_bfloat16 lo = __float2bfloat16(hv - __bfloat162float(hi));
            st_cg_u16(g_Hhi[s & 1] + hwr, hi);
            st_cg_u16(g_Hlo[s & 1] + hwr, lo);
            if (s == SQ - 1) {
                out[hwr]         = hv;
                out[32768 + hwr] = c_reg;
            }
        }
        __syncthreads();
        if (tid == 0)
            asm volatile("red.release.gpu.global.add.u32 [%0], %1;"
                         :: "l"(&g_cnt[bg]), "r"(1u) : "memory");
    }
}

// ---------------- launch ----------------
extern "C" void kernel_launch(void* const* d_in, const int* in_sizes, int n_in,
                              void* d_out, int out_size)
{
    const float* x = (const float*)d_in[0];
    cudaFuncSetAttribute(lstm_hmma_kernel, cudaFuncAttributeMaxDynamicSharedMemorySize, LSMEM_BYTES);
    cudaFuncSetAttribute(xproj_hmma_kernel, cudaFuncAttributeMaxDynamicSharedMemorySize, XSMEM_BYTES);

    prep_kernel<<<6281, 256>>>(
        (const float*)d_in[1],  (const float*)d_in[2],  (const float*)d_in[3],  (const float*)d_in[4],
        (const float*)d_in[5],  (const float*)d_in[6],  (const float*)d_in[7],  (const float*)d_in[8],
        (const float*)d_in[9],  (const float*)d_in[10], (const float*)d_in[11], (const float*)d_in[12],
        (const float*)d_in[13], (const float*)d_in[14], (const float*)d_in[15], (const float*)d_in[16]);

    xsplit_kernel<<<16384, 256>>>(x);

    dim3 g1(16, 512);
    xproj_hmma_kernel<<<g1, 256, XSMEM_BYTES>>>();

    lstm_hmma_kernel<<<128, 256, LSMEM_BYTES>>>((float*)d_out);
}

// round 8
// speedup vs baseline: 1.5650x; 1.1243x over previous
#include <cuda_runtime.h>
#include <cuda_bf16.h>
#include <cstdint>
#include <cstring>

#define SQ 1024
#define BA 64
#define IN 256
#define HD 512
#define G4 2048
#define WPAD 520

// ---------------- device scratch ----------------
__device__ __align__(16) float g_BIAS[G4];
__device__ __align__(16) __nv_bfloat16 g_WXhi[G4 * IN];        // [n][i] natural
__device__ __align__(16) __nv_bfloat16 g_WXlo[G4 * IN];
__device__ __align__(16) __nv_bfloat16 g_Xhi[(size_t)65536 * IN];  // [m=(s<<6)|b][i]
__device__ __align__(16) __nv_bfloat16 g_Xlo[(size_t)65536 * IN];
__device__ __align__(16) __nv_bfloat16 g_WHhi[32 * 64 * 512];  // [hg][row=g*16+jl][k]
__device__ __align__(16) __nv_bfloat16 g_WHlo[32 * 64 * 512];
__device__ __align__(16) float g_XG[(size_t)SQ * BA * G4];
__device__ __align__(16) __nv_bfloat16 g_Hhi[2][BA * HD];
__device__ __align__(16) __nv_bfloat16 g_Hlo[2][BA * HD];
__device__ unsigned g_cnt[4];

// ---------------- helpers ----------------
__device__ __forceinline__ uint32_t smem_u32(const void* p) {
    uint32_t a;
    asm("{ .reg .u64 t; cvta.to.shared.u64 t, %1; cvt.u32.u64 %0, t; }" : "=r"(a) : "l"(p));
    return a;
}
__device__ __forceinline__ void ldsm4(uint32_t* r, uint32_t a) {
    asm volatile("ldmatrix.sync.aligned.m8n8.x4.shared.b16 {%0,%1,%2,%3}, [%4];"
                 : "=r"(r[0]), "=r"(r[1]), "=r"(r[2]), "=r"(r[3]) : "r"(a));
}
__device__ __forceinline__ void ldsm2(uint32_t* r, uint32_t a) {
    asm volatile("ldmatrix.sync.aligned.m8n8.x2.shared.b16 {%0,%1}, [%2];"
                 : "=r"(r[0]), "=r"(r[1]) : "r"(a));
}
__device__ __forceinline__ void mma16816(float* d, const uint32_t* a, const uint32_t* b) {
    asm volatile("mma.sync.aligned.m16n8k16.row.col.f32.bf16.bf16.f32 "
                 "{%0,%1,%2,%3}, {%4,%5,%6,%7}, {%8,%9}, {%0,%1,%2,%3};"
                 : "+f"(d[0]), "+f"(d[1]), "+f"(d[2]), "+f"(d[3])
                 : "r"(a[0]), "r"(a[1]), "r"(a[2]), "r"(a[3]), "r"(b[0]), "r"(b[1]));
}
__device__ __forceinline__ void st_cg_u16(__nv_bfloat16* p, __nv_bfloat16 v) {
    unsigned short us;
    memcpy(&us, &v, 2);
    asm volatile("st.global.cg.u16 [%0], %1;" :: "l"(p), "h"(us) : "memory");
}

// ---------------- prep ----------------
__global__ void prep_kernel(
    const float* Wxi, const float* bxi, const float* Whi, const float* bhi,
    const float* Wxf, const float* bxf, const float* Whf, const float* bhf,
    const float* Wxo, const float* bxo, const float* Who, const float* bho,
    const float* Wxc, const float* bxc, const float* Whc, const float* bhc)
{
    const float* Wx[4] = {Wxi, Wxf, Wxo, Wxc};
    const float* bx[4] = {bxi, bxf, bxo, bxc};
    const float* Wh[4] = {Whi, Whf, Who, Whc};
    const float* bh[4] = {bhi, bhf, bho, bhc};
    long idx = (long)blockIdx.x * 256 + threadIdx.x;

    if (idx < 524288L) {
        int i = (int)(idx & 255), n = (int)(idx >> 8);
        int g = n >> 9, j = n & 511;
        float w = Wx[g][(size_t)j * IN + i];
        __nv_bfloat16 hi = __float2bfloat16(w);
        g_WXhi[idx] = hi;
        g_WXlo[idx] = __float2bfloat16(w - __bfloat162float(hi));
        return;
    }
    idx -= 524288L;
    if (idx < 2048L) {
        int g = (int)(idx >> 9), j = (int)(idx & 511);
        g_BIAS[idx] = bx[g][j] + bh[g][j];
        return;
    }
    idx -= 2048L;
    if (idx < 1048576L) {
        int k = (int)(idx & 511);
        int r = (int)((idx >> 9) & 63);
        int hg = (int)(idx >> 15);
        int g = r >> 4, j = hg * 16 + (r & 15);
        float w = Wh[g][(size_t)j * HD + k];
        __nv_bfloat16 hi = __float2bfloat16(w);
        g_WHhi[idx] = hi;
        g_WHlo[idx] = __float2bfloat16(w - __bfloat162float(hi));
        return;
    }
    idx -= 1048576L;
    if (idx < 32768L) {
        __nv_bfloat16 z = __float2bfloat16(0.f);
        g_Hhi[1][idx] = z;
        g_Hlo[1][idx] = z;
        return;
    }
    idx -= 32768L;
    if (idx < 4L) g_cnt[idx] = 0u;
}

// ---------------- x split ----------------
__global__ __launch_bounds__(256) void xsplit_kernel(const float* __restrict__ x)
{
    long idx = (long)blockIdx.x * 256 + threadIdx.x;
    long e = idx * 4;
    int i = (int)(e & 255);
    int s = (int)((e >> 8) & 1023);
    int b = (int)(e >> 18);
    float4 v = __ldg((const float4*)(x + e));
    float vv[4] = {v.x, v.y, v.z, v.w};
    __nv_bfloat16 h[4], l[4];
#pragma unroll
    for (int t = 0; t < 4; t++) {
        h[t] = __float2bfloat16(vv[t]);
        l[t] = __float2bfloat16(vv[t] - __bfloat162float(h[t]));
    }
    size_t off = (((size_t)((s << 6) | b)) << 8) + i;
    *(uint2*)(g_Xhi + off) = *(uint2*)h;
    *(uint2*)(g_Xlo + off) = *(uint2*)l;
}

// ---------------- xproj: HMMA (proven in R7) ----------------
#define XPAD 136
#define XS_AH 0
#define XS_AL (128 * XPAD * 2)
#define XS_BH (2 * 128 * XPAD * 2)
#define XS_BL (3 * 128 * XPAD * 2)
#define XSMEM_BYTES (4 * 128 * XPAD * 2)

__global__ __launch_bounds__(256, 1) void xproj_hmma_kernel()
{
    extern __shared__ char sm[];
    int tid = threadIdx.x;
    int wid = tid >> 5, lane = tid & 31;
    int n0 = blockIdx.x * 128, m0 = blockIdx.y * 128;
    int mh = wid & 1, nh = wid >> 1;

    uint32_t smb = smem_u32(sm);
    int arow = lane & 15, ak = (lane >= 16) ? 8 : 0;
    uint32_t aBH = smb + XS_AH + ((mh * 64 + arow) * XPAD + ak) * 2;
    uint32_t aBL = smb + XS_AL + ((mh * 64 + arow) * XPAD + ak) * 2;
    int brow = lane & 7, bk = (lane & 8) ? 8 : 0;
    uint32_t bBH = smb + XS_BH + ((nh * 32 + brow) * XPAD + bk) * 2;
    uint32_t bBL = smb + XS_BL + ((nh * 32 + brow) * XPAD + bk) * 2;

    float d[4][4][4];
#pragma unroll
    for (int mi = 0; mi < 4; mi++)
#pragma unroll
        for (int ni = 0; ni < 4; ni++)
#pragma unroll
            for (int q = 0; q < 4; q++) d[mi][ni][q] = 0.f;

    int fr = tid >> 1, fh = (tid & 1) * 64;
#pragma unroll
    for (int kc = 0; kc < 2; kc++) {
        int k0 = kc * 128;
        {
            const uint4* sah = (const uint4*)(g_Xhi + (((size_t)(m0 + fr)) << 8) + k0 + fh);
            const uint4* sal = (const uint4*)(g_Xlo + (((size_t)(m0 + fr)) << 8) + k0 + fh);
            const uint4* sbh = (const uint4*)(g_WXhi + (((size_t)(n0 + fr)) << 8) + k0 + fh);
            const uint4* sbl = (const uint4*)(g_WXlo + (((size_t)(n0 + fr)) << 8) + k0 + fh);
            uint4* dah = (uint4*)(sm + XS_AH + (fr * XPAD + fh) * 2);
            uint4* dal = (uint4*)(sm + XS_AL + (fr * XPAD + fh) * 2);
            uint4* dbh = (uint4*)(sm + XS_BH + (fr * XPAD + fh) * 2);
            uint4* dbl = (uint4*)(sm + XS_BL + (fr * XPAD + fh) * 2);
#pragma unroll
            for (int c = 0; c < 8; c++) {
                dah[c] = __ldg(sah + c);
                dal[c] = __ldg(sal + c);
                dbh[c] = __ldg(sbh + c);
                dbl[c] = __ldg(sbl + c);
            }
        }
        __syncthreads();
#pragma unroll
        for (int ks = 0; ks < 8; ks++) {
            uint32_t ko = (uint32_t)ks * 32;
            uint32_t ah[4][4], al[4][4], bh[4][2], bl[4][2];
#pragma unroll
            for (int mi = 0; mi < 4; mi++) {
                ldsm4(ah[mi], aBH + mi * (16 * XPAD * 2) + ko);
                ldsm4(al[mi], aBL + mi * (16 * XPAD * 2) + ko);
            }
#pragma unroll
            for (int ni = 0; ni < 4; ni++) {
                ldsm2(bh[ni], bBH + ni * (8 * XPAD * 2) + ko);
                ldsm2(bl[ni], bBL + ni * (8 * XPAD * 2) + ko);
            }
#pragma unroll
            for (int mi = 0; mi < 4; mi++)
#pragma unroll
                for (int ni = 0; ni < 4; ni++) {
                    mma16816(d[mi][ni], ah[mi], bh[ni]);
                    mma16816(d[mi][ni], ah[mi], bl[ni]);
                    mma16816(d[mi][ni], al[mi], bh[ni]);
                }
        }
        __syncthreads();
    }

    int row_l = lane >> 2, col_l = (lane & 3) * 2;
#pragma unroll
    for (int mi = 0; mi < 4; mi++)
#pragma unroll
        for (int ni = 0; ni < 4; ni++) {
            int gr = m0 + mh * 64 + mi * 16 + row_l;
            int gc = n0 + nh * 32 + ni * 8 + col_l;
            float2 bb = *(const float2*)(g_BIAS + gc);
            float* o = g_XG + (size_t)gr * G4 + gc;
            *(float2*)o = make_float2(d[mi][ni][0] + bb.x, d[mi][ni][1] + bb.y);
            *(float2*)(o + 8 * G4) = make_float2(d[mi][ni][2] + bb.x, d[mi][ni][3] + bb.y);
        }
}

// ---------------- lstm: persistent HMMA recurrence (512 thr, K-split, 3 acc sets) ----------------
#define OFF_WHI  0
#define OFF_WLO  (64 * WPAD * 2)
#define OFF_HHI  (OFF_WLO + 64 * WPAD * 2)
#define OFF_HLO  (OFF_HHI + 16 * WPAD * 2)
#define OFF_CRED (OFF_HLO + 16 * WPAD * 2)
#define LSMEM_BYTES (OFF_CRED + 2 * 64 * 17 * 4)

__global__ __launch_bounds__(512, 1) void lstm_hmma_kernel(float* __restrict__ out)
{
    extern __shared__ char sm[];
    int tid = threadIdx.x;
    int wid = tid >> 5, lane = tid & 31;
    int bg = blockIdx.x >> 5;
    int hg = blockIdx.x & 31;
    int mw = wid & 3;            // M quarter (16 rows)
    int nh = (wid >> 2) & 1;     // N half (8 batches)
    int kh = wid >> 3;           // K half (256 k)

    {   // resident weights: 512 threads, 8 uint4 each per buffer
        int r = tid >> 3, part = tid & 7;
        const uint4* shi = (const uint4*)(g_WHhi + ((size_t)(hg * 64 + r) << 9) + part * 64);
        const uint4* slo = (const uint4*)(g_WHlo + ((size_t)(hg * 64 + r) << 9) + part * 64);
        uint4* dhi = (uint4*)(sm + OFF_WHI + (r * WPAD + part * 64) * 2);
        uint4* dlo = (uint4*)(sm + OFF_WLO + (r * WPAD + part * 64) * 2);
#pragma unroll
        for (int i = 0; i < 8; i++) { dhi[i] = shi[i]; dlo[i] = slo[i]; }
    }

    uint32_t smb = smem_u32(sm);
    int arow = lane & 15, akoff = (lane >= 16) ? 8 : 0;
    uint32_t aHiB = smb + OFF_WHI + ((mw * 16 + arow) * WPAD + kh * 256 + akoff) * 2;
    uint32_t aLoB = smb + OFF_WLO + ((mw * 16 + arow) * WPAD + kh * 256 + akoff) * 2;
    int brow = lane & 7, bkoff = (lane & 8) ? 8 : 0;
    uint32_t bHiB = smb + OFF_HHI + ((nh * 8 + brow) * WPAD + kh * 256 + bkoff) * 2;
    uint32_t bLoB = smb + OFF_HLO + ((nh * 8 + brow) * WPAD + kh * 256 + bkoff) * 2;

    float* Cred = (float*)(sm + OFF_CRED);     // [2][64][17]
    float* Credk = Cred + kh * (64 * 17);
    int drow = mw * 16 + (lane >> 2), dcol = nh * 8 + (lane & 3) * 2;

    int jl = tid & 15, b = (tid >> 4) & 15;    // pointwise cell (tid<256)
    int hwr = (bg * 16 + b) * HD + hg * 16 + jl;
    float c_reg = 0.f;

    __syncthreads();

    for (int s = 0; s < SQ; s++) {
        float xgi, xgf, xgo, xgc;
        if (tid < 256) {   // prefetch xg, hidden behind barrier wait
            const float* xgr = g_XG + (((size_t)(s * 64 + bg * 16 + b)) << 11) + hg * 16 + jl;
            xgi = __ldg(xgr);
            xgf = __ldg(xgr + 512);
            xgo = __ldg(xgr + 1024);
            xgc = __ldg(xgr + 1536);
        }
        if (s > 0 && tid == 0) {
            unsigned tgt = 32u * (unsigned)s;
            long fuse = 400000000L;
            unsigned v;
            do {
                asm volatile("ld.acquire.gpu.global.u32 %0, [%1];"
                             : "=r"(v) : "l"(&g_cnt[bg]) : "memory");
            } while (v < tgt && --fuse > 0);
        }
        __syncthreads();

        {   // h_{s-1} -> SMEM [16][WPAD] hi/lo; 512 threads, 2 uint4 each
            int t = tid & 255;
            int row = t >> 4, ch = (t & 15) * 32;
            const __nv_bfloat16* hb = (tid < 256) ? g_Hhi[(s + 1) & 1] : g_Hlo[(s + 1) & 1];
            const uint4* srcv = (const uint4*)(hb + (size_t)(bg * 16 + row) * HD + ch);
            uint4* dst = (uint4*)(sm + ((tid < 256) ? OFF_HHI : OFF_HLO) + (row * WPAD + ch) * 2);
            dst[0] = __ldcg(srcv);
            dst[1] = __ldcg(srcv + 1);
            dst[2] = __ldcg(srcv + 2);
            dst[3] = __ldcg(srcv + 3);
        }
        __syncthreads();

        // 3 independent accumulator sets -> no RAW chain between terms
        float da[4] = {0, 0, 0, 0}, db[4] = {0, 0, 0, 0}, dc[4] = {0, 0, 0, 0};
#pragma unroll 4
        for (int ks = 0; ks < 16; ks++) {
            uint32_t ko = (uint32_t)ks * 32;
            uint32_t ahi[4], alo[4], bhi[2], blo[2];
            ldsm4(ahi, aHiB + ko);
            ldsm2(bhi, bHiB + ko);
            ldsm2(blo, bLoB + ko);
            ldsm4(alo, aLoB + ko);
            mma16816(da, ahi, bhi);
            mma16816(db, ahi, blo);
            mma16816(dc, alo, bhi);
        }
        Credk[drow * 17 + dcol]           = da[0] + db[0] + dc[0];
        Credk[drow * 17 + dcol + 1]       = da[1] + db[1] + dc[1];
        Credk[(drow + 8) * 17 + dcol]     = da[2] + db[2] + dc[2];
        Credk[(drow + 8) * 17 + dcol + 1] = da[3] + db[3] + dc[3];
        __syncthreads();

        if (tid < 256) {   // pointwise: sum both K halves + xg
            float gi = Cred[jl * 17 + b]        + Cred[64 * 17 + jl * 17 + b]        + xgi;
            float gf = Cred[(16 + jl) * 17 + b] + Cred[64 * 17 + (16 + jl) * 17 + b] + xgf;
            float go = Cred[(32 + jl) * 17 + b] + Cred[64 * 17 + (32 + jl) * 17 + b] + xgo;
            float gc = Cred[(48 + jl) * 17 + b] + Cred[64 * 17 + (48 + jl) * 17 + b] + xgc;
            float iv = 1.f / (1.f + __expf(-gi));
            float fv = 1.f / (1.f + __expf(-gf));
            float ov = 1.f / (1.f + __expf(-go));
            float gv = tanhf(gc);
            c_reg = fv * c_reg + iv * gv;
            float hv = ov * tanhf(c_reg);
            __nv_bfloat16 hi = __float2bfloat16(hv);
            __nv_bfloat16 lo = __float2bfloat16(hv - __bfloat162float(hi));
            st_cg_u16(g_Hhi[s & 1] + hwr, hi);
            st_cg_u16(g_Hlo[s & 1] + hwr, lo);
            if (s == SQ - 1) {
                out[hwr]         = hv;
                out[32768 + hwr] = c_reg;
            }
        }
        __syncthreads();
        if (tid == 0)
            asm volatile("red.release.gpu.global.add.u32 [%0], %1;"
                         :: "l"(&g_cnt[bg]), "r"(1u) : "memory");
    }
}

// ---------------- launch ----------------
extern "C" void kernel_launch(void* const* d_in, const int* in_sizes, int n_in,
                              void* d_out, int out_size)
{
    const float* x = (const float*)d_in[0];
    cudaFuncSetAttribute(lstm_hmma_kernel, cudaFuncAttributeMaxDynamicSharedMemorySize, LSMEM_BYTES);
    cudaFuncSetAttribute(xproj_hmma_kernel, cudaFuncAttributeMaxDynamicSharedMemorySize, XSMEM_BYTES);

    prep_kernel<<<6281, 256>>>(
        (const float*)d_in[1],  (const float*)d_in[2],  (const float*)d_in[3],  (const float*)d_in[4],
        (const float*)d_in[5],  (const float*)d_in[6],  (const float*)d_in[7],  (const float*)d_in[8],
        (const float*)d_in[9],  (const float*)d_in[10], (const float*)d_in[11], (const float*)d_in[12],
        (const float*)d_in[13], (const float*)d_in[14], (const float*)d_in[15], (const float*)d_in[16]);

    xsplit_kernel<<<16384, 256>>>(x);

    dim3 g1(16, 512);
    xproj_hmma_kernel<<<g1, 256, XSMEM_BYTES>>>();

    lstm_hmma_kernel<<<128, 512, LSMEM_BYTES>>>((float*)d_out);
}

// round 9
// speedup vs baseline: 1.9671x; 1.2569x over previous
#include <cuda_runtime.h>
#include <cuda_bf16.h>
#include <cuda_fp16.h>
#include <cstdint>
#include <cstring>

#define SQ 1024
#define BA 64
#define IN 256
#define HD 512
#define G4 2048
#define WPAD 520

// ---------------- device scratch ----------------
__device__ __align__(16) float g_BIAS[G4];
__device__ __align__(16) __nv_bfloat16 g_WXhi[G4 * IN];        // [n][i]
__device__ __align__(16) __nv_bfloat16 g_WXlo[G4 * IN];
__device__ __align__(16) __nv_bfloat16 g_Xhi[(size_t)65536 * IN];
__device__ __align__(16) __nv_bfloat16 g_Xlo[(size_t)65536 * IN];
__device__ __align__(16) __half g_WHhi[32 * 64 * 512];         // [hg][row=g*16+jl][k] fp16
__device__ __align__(16) __half g_WHlo[32 * 64 * 512];         // residual * 4096, fp16
__device__ __align__(16) float g_XG[(size_t)SQ * BA * G4];
__device__ __align__(16) __half g_Hh[2][BA * HD];              // h exchange, single fp16
__device__ unsigned g_cnt[4];

// ---------------- helpers ----------------
__device__ __forceinline__ uint32_t smem_u32(const void* p) {
    uint32_t a;
    asm("{ .reg .u64 t; cvta.to.shared.u64 t, %1; cvt.u32.u64 %0, t; }" : "=r"(a) : "l"(p));
    return a;
}
__device__ __forceinline__ void ldsm4(uint32_t* r, uint32_t a) {
    asm volatile("ldmatrix.sync.aligned.m8n8.x4.shared.b16 {%0,%1,%2,%3}, [%4];"
                 : "=r"(r[0]), "=r"(r[1]), "=r"(r[2]), "=r"(r[3]) : "r"(a));
}
__device__ __forceinline__ void ldsm2(uint32_t* r, uint32_t a) {
    asm volatile("ldmatrix.sync.aligned.m8n8.x2.shared.b16 {%0,%1}, [%2];"
                 : "=r"(r[0]), "=r"(r[1]) : "r"(a));
}
__device__ __forceinline__ void mma16816(float* d, const uint32_t* a, const uint32_t* b) {
    asm volatile("mma.sync.aligned.m16n8k16.row.col.f32.bf16.bf16.f32 "
                 "{%0,%1,%2,%3}, {%4,%5,%6,%7}, {%8,%9}, {%0,%1,%2,%3};"
                 : "+f"(d[0]), "+f"(d[1]), "+f"(d[2]), "+f"(d[3])
                 : "r"(a[0]), "r"(a[1]), "r"(a[2]), "r"(a[3]), "r"(b[0]), "r"(b[1]));
}
__device__ __forceinline__ void mma16816h(float* d, const uint32_t* a, const uint32_t* b) {
    asm volatile("mma.sync.aligned.m16n8k16.row.col.f32.f16.f16.f32 "
                 "{%0,%1,%2,%3}, {%4,%5,%6,%7}, {%8,%9}, {%0,%1,%2,%3};"
                 : "+f"(d[0]), "+f"(d[1]), "+f"(d[2]), "+f"(d[3])
                 : "r"(a[0]), "r"(a[1]), "r"(a[2]), "r"(a[3]), "r"(b[0]), "r"(b[1]));
}
__device__ __forceinline__ void st_cg_u16h(__half* p, __half v) {
    unsigned short us;
    memcpy(&us, &v, 2);
    asm volatile("st.global.cg.u16 [%0], %1;" :: "l"(p), "h"(us) : "memory");
}

// ---------------- prep ----------------
__global__ void prep_kernel(
    const float* Wxi, const float* bxi, const float* Whi, const float* bhi,
    const float* Wxf, const float* bxf, const float* Whf, const float* bhf,
    const float* Wxo, const float* bxo, const float* Who, const float* bho,
    const float* Wxc, const float* bxc, const float* Whc, const float* bhc)
{
    const float* Wx[4] = {Wxi, Wxf, Wxo, Wxc};
    const float* bx[4] = {bxi, bxf, bxo, bxc};
    const float* Wh[4] = {Whi, Whf, Who, Whc};
    const float* bh[4] = {bhi, bhf, bho, bhc};
    long idx = (long)blockIdx.x * 256 + threadIdx.x;

    if (idx < 524288L) {                       // WX split bf16 (unchanged)
        int i = (int)(idx & 255), n = (int)(idx >> 8);
        int g = n >> 9, j = n & 511;
        float w = Wx[g][(size_t)j * IN + i];
        __nv_bfloat16 hi = __float2bfloat16(w);
        g_WXhi[idx] = hi;
        g_WXlo[idx] = __float2bfloat16(w - __bfloat162float(hi));
        return;
    }
    idx -= 524288L;
    if (idx < 2048L) {
        int g = (int)(idx >> 9), j = (int)(idx & 511);
        g_BIAS[idx] = bx[g][j] + bh[g][j];
        return;
    }
    idx -= 2048L;
    if (idx < 1048576L) {                      // WH split fp16, residual scaled x4096
        int k = (int)(idx & 511);
        int r = (int)((idx >> 9) & 63);
        int hg = (int)(idx >> 15);
        int g = r >> 4, j = hg * 16 + (r & 15);
        float w = Wh[g][(size_t)j * HD + k];
        __half hi = __float2half_rn(w);
        g_WHhi[idx] = hi;
        g_WHlo[idx] = __float2half_rn((w - __half2float(hi)) * 4096.f);
        return;
    }
    idx -= 1048576L;
    if (idx < 32768L) {
        g_Hh[1][idx] = __float2half_rn(0.f);
        return;
    }
    idx -= 32768L;
    if (idx < 4L) g_cnt[idx] = 0u;
}

// ---------------- x split ----------------
__global__ __launch_bounds__(256) void xsplit_kernel(const float* __restrict__ x)
{
    long idx = (long)blockIdx.x * 256 + threadIdx.x;
    long e = idx * 4;
    int i = (int)(e & 255);
    int s = (int)((e >> 8) & 1023);
    int b = (int)(e >> 18);
    float4 v = __ldg((const float4*)(x + e));
    float vv[4] = {v.x, v.y, v.z, v.w};
    __nv_bfloat16 h[4], l[4];
#pragma unroll
    for (int t = 0; t < 4; t++) {
        h[t] = __float2bfloat16(vv[t]);
        l[t] = __float2bfloat16(vv[t] - __bfloat162float(h[t]));
    }
    size_t off = (((size_t)((s << 6) | b)) << 8) + i;
    *(uint2*)(g_Xhi + off) = *(uint2*)h;
    *(uint2*)(g_Xlo + off) = *(uint2*)l;
}

// ---------------- xproj: HMMA (proven) ----------------
#define XPAD 136
#define XS_AH 0
#define XS_AL (128 * XPAD * 2)
#define XS_BH (2 * 128 * XPAD * 2)
#define XS_BL (3 * 128 * XPAD * 2)
#define XSMEM_BYTES (4 * 128 * XPAD * 2)

__global__ __launch_bounds__(256, 1) void xproj_hmma_kernel()
{
    extern __shared__ char sm[];
    int tid = threadIdx.x;
    int wid = tid >> 5, lane = tid & 31;
    int n0 = blockIdx.x * 128, m0 = blockIdx.y * 128;
    int mh = wid & 1, nh = wid >> 1;

    uint32_t smb = smem_u32(sm);
    int arow = lane & 15, ak = (lane >= 16) ? 8 : 0;
    uint32_t aBH = smb + XS_AH + ((mh * 64 + arow) * XPAD + ak) * 2;
    uint32_t aBL = smb + XS_AL + ((mh * 64 + arow) * XPAD + ak) * 2;
    int brow = lane & 7, bk = (lane & 8) ? 8 : 0;
    uint32_t bBH = smb + XS_BH + ((nh * 32 + brow) * XPAD + bk) * 2;
    uint32_t bBL = smb + XS_BL + ((nh * 32 + brow) * XPAD + bk) * 2;

    float d[4][4][4];
#pragma unroll
    for (int mi = 0; mi < 4; mi++)
#pragma unroll
        for (int ni = 0; ni < 4; ni++)
#pragma unroll
            for (int q = 0; q < 4; q++) d[mi][ni][q] = 0.f;

    int fr = tid >> 1, fh = (tid & 1) * 64;
#pragma unroll
    for (int kc = 0; kc < 2; kc++) {
        int k0 = kc * 128;
        {
            const uint4* sah = (const uint4*)(g_Xhi + (((size_t)(m0 + fr)) << 8) + k0 + fh);
            const uint4* sal = (const uint4*)(g_Xlo + (((size_t)(m0 + fr)) << 8) + k0 + fh);
            const uint4* sbh = (const uint4*)(g_WXhi + (((size_t)(n0 + fr)) << 8) + k0 + fh);
            const uint4* sbl = (const uint4*)(g_WXlo + (((size_t)(n0 + fr)) << 8) + k0 + fh);
            uint4* dah = (uint4*)(sm + XS_AH + (fr * XPAD + fh) * 2);
            uint4* dal = (uint4*)(sm + XS_AL + (fr * XPAD + fh) * 2);
            uint4* dbh = (uint4*)(sm + XS_BH + (fr * XPAD + fh) * 2);
            uint4* dbl = (uint4*)(sm + XS_BL + (fr * XPAD + fh) * 2);
#pragma unroll
            for (int c = 0; c < 8; c++) {
                dah[c] = __ldg(sah + c);
                dal[c] = __ldg(sal + c);
                dbh[c] = __ldg(sbh + c);
                dbl[c] = __ldg(sbl + c);
            }
        }
        __syncthreads();
#pragma unroll
        for (int ks = 0; ks < 8; ks++) {
            uint32_t ko = (uint32_t)ks * 32;
            uint32_t ah[4][4], al[4][4], bh[4][2], bl[4][2];
#pragma unroll
            for (int mi = 0; mi < 4; mi++) {
                ldsm4(ah[mi], aBH + mi * (16 * XPAD * 2) + ko);
                ldsm4(al[mi], aBL + mi * (16 * XPAD * 2) + ko);
            }
#pragma unroll
            for (int ni = 0; ni < 4; ni++) {
                ldsm2(bh[ni], bBH + ni * (8 * XPAD * 2) + ko);
                ldsm2(bl[ni], bBL + ni * (8 * XPAD * 2) + ko);
            }
#pragma unroll
            for (int mi = 0; mi < 4; mi++)
#pragma unroll
                for (int ni = 0; ni < 4; ni++) {
                    mma16816(d[mi][ni], ah[mi], bh[ni]);
                    mma16816(d[mi][ni], ah[mi], bl[ni]);
                    mma16816(d[mi][ni], al[mi], bh[ni]);
                }
        }
        __syncthreads();
    }

    int row_l = lane >> 2, col_l = (lane & 3) * 2;
#pragma unroll
    for (int mi = 0; mi < 4; mi++)
#pragma unroll
        for (int ni = 0; ni < 4; ni++) {
            int gr = m0 + mh * 64 + mi * 16 + row_l;
            int gc = n0 + nh * 32 + ni * 8 + col_l;
            float2 bb = *(const float2*)(g_BIAS + gc);
            float* o = g_XG + (size_t)gr * G4 + gc;
            *(float2*)o = make_float2(d[mi][ni][0] + bb.x, d[mi][ni][1] + bb.y);
            *(float2*)(o + 8 * G4) = make_float2(d[mi][ni][2] + bb.x, d[mi][ni][3] + bb.y);
        }
}

// ---------------- lstm: persistent fp16 2-term HMMA recurrence ----------------
#define OFF_WHI  0
#define OFF_WLO  (64 * WPAD * 2)
#define OFF_HH   (OFF_WLO + 64 * WPAD * 2)
#define OFF_CRED (OFF_HH + 16 * WPAD * 2)
#define LSMEM_BYTES (OFF_CRED + 2 * 64 * 17 * 4)

__global__ __launch_bounds__(512, 1) void lstm_hmma_kernel(float* __restrict__ out)
{
    extern __shared__ char sm[];
    int tid = threadIdx.x;
    int wid = tid >> 5, lane = tid & 31;
    int bg = blockIdx.x >> 5;
    int hg = blockIdx.x & 31;
    int mw = wid & 3;            // M quarter
    int nh = (wid >> 2) & 1;     // N half
    int kh = wid >> 3;           // K half

    {   // resident weights fp16: [64][512] -> [64][WPAD], hi & lo(scaled)
        int r = tid >> 3, part = tid & 7;
        const uint4* shi = (const uint4*)(g_WHhi + ((size_t)(hg * 64 + r) << 9) + part * 64);
        const uint4* slo = (const uint4*)(g_WHlo + ((size_t)(hg * 64 + r) << 9) + part * 64);
        uint4* dhi = (uint4*)(sm + OFF_WHI + (r * WPAD + part * 64) * 2);
        uint4* dlo = (uint4*)(sm + OFF_WLO + (r * WPAD + part * 64) * 2);
#pragma unroll
        for (int i = 0; i < 8; i++) { dhi[i] = shi[i]; dlo[i] = slo[i]; }
    }

    uint32_t smb = smem_u32(sm);
    int arow = lane & 15, akoff = (lane >= 16) ? 8 : 0;
    uint32_t aHiB = smb + OFF_WHI + ((mw * 16 + arow) * WPAD + kh * 256 + akoff) * 2;
    uint32_t aLoB = smb + OFF_WLO + ((mw * 16 + arow) * WPAD + kh * 256 + akoff) * 2;
    int brow = lane & 7, bkoff = (lane & 8) ? 8 : 0;
    uint32_t bHB = smb + OFF_HH + ((nh * 8 + brow) * WPAD + kh * 256 + bkoff) * 2;

    float* Cred = (float*)(sm + OFF_CRED);     // [2][64][17]
    float* Credk = Cred + kh * (64 * 17);
    int drow = mw * 16 + (lane >> 2), dcol = nh * 8 + (lane & 3) * 2;

    int jl = tid & 15, b = (tid >> 4) & 15;
    int hwr = (bg * 16 + b) * HD + hg * 16 + jl;
    float c_reg = 0.f;

    __syncthreads();

    for (int s = 0; s < SQ; s++) {
        float xgi, xgf, xgo, xgc;
        if (tid < 256) {   // xg prefetch, hidden behind barrier
            const float* xgr = g_XG + (((size_t)(s * 64 + bg * 16 + b)) << 11) + hg * 16 + jl;
            xgi = __ldg(xgr);
            xgf = __ldg(xgr + 512);
            xgo = __ldg(xgr + 1024);
            xgc = __ldg(xgr + 1536);
        }
        if (s > 0 && tid == 0) {
            unsigned tgt = 32u * (unsigned)s;
            long fuse = 400000000L;
            unsigned v;
            do {
                asm volatile("ld.acquire.gpu.global.u32 %0, [%1];"
                             : "=r"(v) : "l"(&g_cnt[bg]) : "memory");
            } while (v < tgt && --fuse > 0);
        }
        __syncthreads();

        {   // h_{s-1} fp16 -> SMEM [16][WPAD]; 512 threads x 32B
            int row = tid >> 5, ch = (tid & 31) * 16;
            const uint4* srcv = (const uint4*)(g_Hh[(s + 1) & 1] + (size_t)(bg * 16 + row) * HD + ch);
            uint4* dst = (uint4*)(sm + OFF_HH + (row * WPAD + ch) * 2);
            dst[0] = __ldcg(srcv);
            dst[1] = __ldcg(srcv + 1);
        }
        __syncthreads();

        float da[4] = {0, 0, 0, 0}, db[4] = {0, 0, 0, 0};
#pragma unroll 4
        for (int ks = 0; ks < 16; ks++) {
            uint32_t ko = (uint32_t)ks * 32;
            uint32_t ahi[4], alo[4], bh[2];
            ldsm4(ahi, aHiB + ko);
            ldsm2(bh, bHB + ko);
            ldsm4(alo, aLoB + ko);
            mma16816h(da, ahi, bh);
            mma16816h(db, alo, bh);
        }
        const float SC = 1.f / 4096.f;
        Credk[drow * 17 + dcol]           = da[0] + db[0] * SC;
        Credk[drow * 17 + dcol + 1]       = da[1] + db[1] * SC;
        Credk[(drow + 8) * 17 + dcol]     = da[2] + db[2] * SC;
        Credk[(drow + 8) * 17 + dcol + 1] = da[3] + db[3] * SC;
        __syncthreads();

        if (tid < 256) {
            float gi = Cred[jl * 17 + b]        + Cred[64 * 17 + jl * 17 + b]        + xgi;
            float gf = Cred[(16 + jl) * 17 + b] + Cred[64 * 17 + (16 + jl) * 17 + b] + xgf;
            float go = Cred[(32 + jl) * 17 + b] + Cred[64 * 17 + (32 + jl) * 17 + b] + xgo;
            float gc = Cred[(48 + jl) * 17 + b] + Cred[64 * 17 + (48 + jl) * 17 + b] + xgc;
            float iv = 1.f / (1.f + __expf(-gi));
            float fv = 1.f / (1.f + __expf(-gf));
            float ov = 1.f / (1.f + __expf(-go));
            float gv = tanhf(gc);
            c_reg = fv * c_reg + iv * gv;
            float hv = ov * tanhf(c_reg);
            st_cg_u16h(g_Hh[s & 1] + hwr, __float2half_rn(hv));
            if (s == SQ - 1) {
                out[hwr]         = hv;
                out[32768 + hwr] = c_reg;
            }
        }
        __syncthreads();
        if (tid == 0)
            asm volatile("red.release.gpu.global.add.u32 [%0], %1;"
                         :: "l"(&g_cnt[bg]), "r"(1u) : "memory");
    }
}

// ---------------- launch ----------------
extern "C" void kernel_launch(void* const* d_in, const int* in_sizes, int n_in,
                              void* d_out, int out_size)
{
    const float* x = (const float*)d_in[0];
    cudaFuncSetAttribute(lstm_hmma_kernel, cudaFuncAttributeMaxDynamicSharedMemorySize, LSMEM_BYTES);
    cudaFuncSetAttribute(xproj_hmma_kernel, cudaFuncAttributeMaxDynamicSharedMemorySize, XSMEM_BYTES);

    prep_kernel<<<6281, 256>>>(
        (const float*)d_in[1],  (const float*)d_in[2],  (const float*)d_in[3],  (const float*)d_in[4],
        (const float*)d_in[5],  (const float*)d_in[6],  (const float*)d_in[7],  (const float*)d_in[8],
        (const float*)d_in[9],  (const float*)d_in[10], (const float*)d_in[11], (const float*)d_in[12],
        (const float*)d_in[13], (const float*)d_in[14], (const float*)d_in[15], (const float*)d_in[16]);

    xsplit_kernel<<<16384, 256>>>(x);

    dim3 g1(16, 512);
    xproj_hmma_kernel<<<g1, 256, XSMEM_BYTES>>>();

    lstm_hmma_kernel<<<128, 512, LSMEM_BYTES>>>((float*)d_out);
}

// round 10
// speedup vs baseline: 2.5635x; 1.3032x over previous
#include <cuda_runtime.h>
#include <cuda_bf16.h>
#include <cuda_fp16.h>
#include <cstdint>
#include <cstring>

#define SQ 1024
#define BA 64
#define IN 256
#define HD 512
#define G4 2048
#define WPAD 520

// ---------------- device scratch ----------------
__device__ __align__(16) float g_BIAS[G4];
__device__ __align__(16) __half g_WXh[G4 * IN];            // [n][i] fp16
__device__ __align__(16) __half g_Xh[(size_t)65536 * IN];  // [m=(s<<6)|b][i] fp16
__device__ __align__(16) __half g_WHh[32 * 64 * 512];      // [hg][row=g*16+jl][k] fp16
__device__ __align__(16) float g_XG[(size_t)SQ * BA * G4];
__device__ __align__(16) __half g_Hh[2][BA * HD];          // h exchange fp16
__device__ unsigned g_cnt[4];

// ---------------- helpers ----------------
__device__ __forceinline__ uint32_t smem_u32(const void* p) {
    uint32_t a;
    asm("{ .reg .u64 t; cvta.to.shared.u64 t, %1; cvt.u32.u64 %0, t; }" : "=r"(a) : "l"(p));
    return a;
}
__device__ __forceinline__ void ldsm4(uint32_t* r, uint32_t a) {
    asm volatile("ldmatrix.sync.aligned.m8n8.x4.shared.b16 {%0,%1,%2,%3}, [%4];"
                 : "=r"(r[0]), "=r"(r[1]), "=r"(r[2]), "=r"(r[3]) : "r"(a));
}
__device__ __forceinline__ void ldsm2(uint32_t* r, uint32_t a) {
    asm volatile("ldmatrix.sync.aligned.m8n8.x2.shared.b16 {%0,%1}, [%2];"
                 : "=r"(r[0]), "=r"(r[1]) : "r"(a));
}
__device__ __forceinline__ void mma16816h(float* d, const uint32_t* a, const uint32_t* b) {
    asm volatile("mma.sync.aligned.m16n8k16.row.col.f32.f16.f16.f32 "
                 "{%0,%1,%2,%3}, {%4,%5,%6,%7}, {%8,%9}, {%0,%1,%2,%3};"
                 : "+f"(d[0]), "+f"(d[1]), "+f"(d[2]), "+f"(d[3])
                 : "r"(a[0]), "r"(a[1]), "r"(a[2]), "r"(a[3]), "r"(b[0]), "r"(b[1]));
}
__device__ __forceinline__ void st_cg_u16h(__half* p, __half v) {
    unsigned short us;
    memcpy(&us, &v, 2);
    asm volatile("st.global.cg.u16 [%0], %1;" :: "l"(p), "h"(us) : "memory");
}

// ---------------- prep ----------------
__global__ void prep_kernel(
    const float* Wxi, const float* bxi, const float* Whi, const float* bhi,
    const float* Wxf, const float* bxf, const float* Whf, const float* bhf,
    const float* Wxo, const float* bxo, const float* Who, const float* bho,
    const float* Wxc, const float* bxc, const float* Whc, const float* bhc)
{
    const float* Wx[4] = {Wxi, Wxf, Wxo, Wxc};
    const float* bx[4] = {bxi, bxf, bxo, bxc};
    const float* Wh[4] = {Whi, Whf, Who, Whc};
    const float* bh[4] = {bhi, bhf, bho, bhc};
    long idx = (long)blockIdx.x * 256 + threadIdx.x;

    if (idx < 524288L) {                       // WX fp16, [n][i]
        int i = (int)(idx & 255), n = (int)(idx >> 8);
        int g = n >> 9, j = n & 511;
        g_WXh[idx] = __float2half_rn(Wx[g][(size_t)j * IN + i]);
        return;
    }
    idx -= 524288L;
    if (idx < 2048L) {
        int g = (int)(idx >> 9), j = (int)(idx & 511);
        g_BIAS[idx] = bx[g][j] + bh[g][j];
        return;
    }
    idx -= 2048L;
    if (idx < 1048576L) {                      // WH fp16
        int k = (int)(idx & 511);
        int r = (int)((idx >> 9) & 63);
        int hg = (int)(idx >> 15);
        int g = r >> 4, j = hg * 16 + (r & 15);
        g_WHh[idx] = __float2half_rn(Wh[g][(size_t)j * HD + k]);
        return;
    }
    idx -= 1048576L;
    if (idx < 32768L) {
        g_Hh[1][idx] = __float2half_rn(0.f);
        return;
    }
    idx -= 32768L;
    if (idx < 4L) g_cnt[idx] = 0u;
}

// ---------------- x -> fp16, layout [(s<<6)|b][i] ----------------
__global__ __launch_bounds__(256) void xsplit_kernel(const float* __restrict__ x)
{
    long idx = (long)blockIdx.x * 256 + threadIdx.x;
    long e = idx * 4;
    int i = (int)(e & 255);
    int s = (int)((e >> 8) & 1023);
    int b = (int)(e >> 18);
    float4 v = __ldg((const float4*)(x + e));
    __half h[4] = {__float2half_rn(v.x), __float2half_rn(v.y),
                   __float2half_rn(v.z), __float2half_rn(v.w)};
    size_t off = (((size_t)((s << 6) | b)) << 8) + i;
    *(uint2*)(g_Xh + off) = *(uint2*)h;
}

// ---------------- xproj: single-term fp16 HMMA ----------------
#define XPAD 136
#define XS_A 0
#define XS_B (128 * XPAD * 2)
#define XSMEM_BYTES (2 * 128 * XPAD * 2)

__global__ __launch_bounds__(256, 1) void xproj_hmma_kernel()
{
    extern __shared__ char sm[];
    int tid = threadIdx.x;
    int wid = tid >> 5, lane = tid & 31;
    int n0 = blockIdx.x * 128, m0 = blockIdx.y * 128;
    int mh = wid & 1, nh = wid >> 1;

    uint32_t smb = smem_u32(sm);
    int arow = lane & 15, ak = (lane >= 16) ? 8 : 0;
    uint32_t aB = smb + XS_A + ((mh * 64 + arow) * XPAD + ak) * 2;
    int brow = lane & 7, bk = (lane & 8) ? 8 : 0;
    uint32_t bB = smb + XS_B + ((nh * 32 + brow) * XPAD + bk) * 2;

    float d[4][4][4];
#pragma unroll
    for (int mi = 0; mi < 4; mi++)
#pragma unroll
        for (int ni = 0; ni < 4; ni++)
#pragma unroll
            for (int q = 0; q < 4; q++) d[mi][ni][q] = 0.f;

    int fr = tid >> 1, fh = (tid & 1) * 64;
#pragma unroll
    for (int kc = 0; kc < 2; kc++) {
        int k0 = kc * 128;
        {
            const uint4* sa = (const uint4*)(g_Xh + (((size_t)(m0 + fr)) << 8) + k0 + fh);
            const uint4* sb = (const uint4*)(g_WXh + (((size_t)(n0 + fr)) << 8) + k0 + fh);
            uint4* da4 = (uint4*)(sm + XS_A + (fr * XPAD + fh) * 2);
            uint4* db4 = (uint4*)(sm + XS_B + (fr * XPAD + fh) * 2);
#pragma unroll
            for (int c = 0; c < 8; c++) {
                da4[c] = __ldg(sa + c);
                db4[c] = __ldg(sb + c);
            }
        }
        __syncthreads();
#pragma unroll
        for (int ks = 0; ks < 8; ks++) {
            uint32_t ko = (uint32_t)ks * 32;
            uint32_t ah[4][4], bh[4][2];
#pragma unroll
            for (int mi = 0; mi < 4; mi++)
                ldsm4(ah[mi], aB + mi * (16 * XPAD * 2) + ko);
#pragma unroll
            for (int ni = 0; ni < 4; ni++)
                ldsm2(bh[ni], bB + ni * (8 * XPAD * 2) + ko);
#pragma unroll
            for (int mi = 0; mi < 4; mi++)
#pragma unroll
                for (int ni = 0; ni < 4; ni++)
                    mma16816h(d[mi][ni], ah[mi], bh[ni]);
        }
        __syncthreads();
    }

    int row_l = lane >> 2, col_l = (lane & 3) * 2;
#pragma unroll
    for (int mi = 0; mi < 4; mi++)
#pragma unroll
        for (int ni = 0; ni < 4; ni++) {
            int gr = m0 + mh * 64 + mi * 16 + row_l;
            int gc = n0 + nh * 32 + ni * 8 + col_l;
            float2 bb = *(const float2*)(g_BIAS + gc);
            float* o = g_XG + (size_t)gr * G4 + gc;
            *(float2*)o = make_float2(d[mi][ni][0] + bb.x, d[mi][ni][1] + bb.y);
            *(float2*)(o + 8 * G4) = make_float2(d[mi][ni][2] + bb.x, d[mi][ni][3] + bb.y);
        }
}

// ---------------- lstm: persistent single-term fp16 HMMA recurrence ----------------
#define OFF_WHI  0
#define OFF_HH   (64 * WPAD * 2)
#define OFF_CRED (OFF_HH + 16 * WPAD * 2)
#define LSMEM_BYTES (OFF_CRED + 2 * 64 * 17 * 4)

__global__ __launch_bounds__(512, 1) void lstm_hmma_kernel(float* __restrict__ out)
{
    extern __shared__ char sm[];
    int tid = threadIdx.x;
    int wid = tid >> 5, lane = tid & 31;
    int bg = blockIdx.x >> 5;
    int hg = blockIdx.x & 31;
    int mw = wid & 3;            // M quarter
    int nh = (wid >> 2) & 1;     // N half
    int kh = wid >> 3;           // K half

    {   // resident weights fp16
        int r = tid >> 3, part = tid & 7;
        const uint4* shi = (const uint4*)(g_WHh + ((size_t)(hg * 64 + r) << 9) + part * 64);
        uint4* dhi = (uint4*)(sm + OFF_WHI + (r * WPAD + part * 64) * 2);
#pragma unroll
        for (int i = 0; i < 8; i++) dhi[i] = shi[i];
    }

    uint32_t smb = smem_u32(sm);
    int arow = lane & 15, akoff = (lane >= 16) ? 8 : 0;
    uint32_t aHiB = smb + OFF_WHI + ((mw * 16 + arow) * WPAD + kh * 256 + akoff) * 2;
    int brow = lane & 7, bkoff = (lane & 8) ? 8 : 0;
    uint32_t bHB = smb + OFF_HH + ((nh * 8 + brow) * WPAD + kh * 256 + bkoff) * 2;

    float* Cred = (float*)(sm + OFF_CRED);     // [2][64][17]
    float* Credk = Cred + kh * (64 * 17);
    int drow = mw * 16 + (lane >> 2), dcol = nh * 8 + (lane & 3) * 2;

    int jl = tid & 15, b = (tid >> 4) & 15;
    int hwr = (bg * 16 + b) * HD + hg * 16 + jl;
    float c_reg = 0.f;

    __syncthreads();

    for (int s = 0; s < SQ; s++) {
        float xgi, xgf, xgo, xgc;
        if (tid < 256) {   // xg prefetch, hidden behind barrier
            const float* xgr = g_XG + (((size_t)(s * 64 + bg * 16 + b)) << 11) + hg * 16 + jl;
            xgi = __ldg(xgr);
            xgf = __ldg(xgr + 512);
            xgo = __ldg(xgr + 1024);
            xgc = __ldg(xgr + 1536);
        }
        if (s > 0 && tid == 0) {
            unsigned tgt = 32u * (unsigned)s;
            long fuse = 400000000L;
            unsigned v;
            do {
                asm volatile("ld.acquire.gpu.global.u32 %0, [%1];"
                             : "=r"(v) : "l"(&g_cnt[bg]) : "memory");
            } while (v < tgt && --fuse > 0);
        }
        __syncthreads();

        {   // h_{s-1} fp16 -> SMEM [16][WPAD]
            int row = tid >> 5, ch = (tid & 31) * 16;
            const uint4* srcv = (const uint4*)(g_Hh[(s + 1) & 1] + (size_t)(bg * 16 + row) * HD + ch);
            uint4* dst = (uint4*)(sm + OFF_HH + (row * WPAD + ch) * 2);
            dst[0] = __ldcg(srcv);
            dst[1] = __ldcg(srcv + 1);
        }
        __syncthreads();

        float da[4] = {0, 0, 0, 0};
#pragma unroll 4
        for (int ks = 0; ks < 16; ks++) {
            uint32_t ko = (uint32_t)ks * 32;
            uint32_t ahi[4], bh[2];
            ldsm4(ahi, aHiB + ko);
            ldsm2(bh, bHB + ko);
            mma16816h(da, ahi, bh);
        }
        Credk[drow * 17 + dcol]           = da[0];
        Credk[drow * 17 + dcol + 1]       = da[1];
        Credk[(drow + 8) * 17 + dcol]     = da[2];
        Credk[(drow + 8) * 17 + dcol + 1] = da[3];
        __syncthreads();

        if (tid < 256) {
            float gi = Cred[jl * 17 + b]        + Cred[64 * 17 + jl * 17 + b]        + xgi;
            float gf = Cred[(16 + jl) * 17 + b] + Cred[64 * 17 + (16 + jl) * 17 + b] + xgf;
            float go = Cred[(32 + jl) * 17 + b] + Cred[64 * 17 + (32 + jl) * 17 + b] + xgo;
            float gc = Cred[(48 + jl) * 17 + b] + Cred[64 * 17 + (48 + jl) * 17 + b] + xgc;
            float iv = 1.f / (1.f + __expf(-gi));
            float fv = 1.f / (1.f + __expf(-gf));
            float ov = 1.f / (1.f + __expf(-go));
            float gv = tanhf(gc);
            c_reg = fv * c_reg + iv * gv;
            float hv = ov * tanhf(c_reg);
            st_cg_u16h(g_Hh[s & 1] + hwr, __float2half_rn(hv));
            if (s == SQ - 1) {
                out[hwr]         = hv;
                out[32768 + hwr] = c_reg;
            }
        }
        __syncthreads();
        if (tid == 0)
            asm volatile("red.release.gpu.global.add.u32 [%0], %1;"
                         :: "l"(&g_cnt[bg]), "r"(1u) : "memory");
    }
}

// ---------------- launch ----------------
extern "C" void kernel_launch(void* const* d_in, const int* in_sizes, int n_in,
                              void* d_out, int out_size)
{
    const float* x = (const float*)d_in[0];
    cudaFuncSetAttribute(lstm_hmma_kernel, cudaFuncAttributeMaxDynamicSharedMemorySize, LSMEM_BYTES);
    cudaFuncSetAttribute(xproj_hmma_kernel, cudaFuncAttributeMaxDynamicSharedMemorySize, XSMEM_BYTES);

    prep_kernel<<<6281, 256>>>(
        (const float*)d_in[1],  (const float*)d_in[2],  (const float*)d_in[3],  (const float*)d_in[4],
        (const float*)d_in[5],  (const float*)d_in[6],  (const float*)d_in[7],  (const float*)d_in[8],
        (const float*)d_in[9],  (const float*)d_in[10], (const float*)d_in[11], (const float*)d_in[12],
        (const float*)d_in[13], (const float*)d_in[14], (const float*)d_in[15], (const float*)d_in[16]);

    xsplit_kernel<<<16384, 256>>>(x);

    dim3 g1(16, 512);
    xproj_hmma_kernel<<<g1, 256, XSMEM_BYTES>>>();

    lstm_hmma_kernel<<<128, 512, LSMEM_BYTES>>>((float*)d_out);
}

// round 13
// speedup vs baseline: 2.8009x; 1.0926x over previous
#include <cuda_runtime.h>
#include <cuda_fp16.h>
#include <cstdint>
#include <cstring>

#define SQ 1024
#define BA 64
#define IN 256
#define HD 512
#define G4 2048
#define WPAD 520

// ---------------- device scratch ----------------
__device__ __align__(16) float g_BIAS[G4];
__device__ __align__(16) __half g_WXh[G4 * IN];            // [n][i] fp16
__device__ __align__(16) __half g_Xh[(size_t)65536 * IN];  // [m=(s<<6)|b][i] fp16
__device__ __align__(16) __half g_WHh[32 * 64 * 512];      // [hg][row=g*16+jl][k] fp16
__device__ __align__(16) float g_XG[(size_t)SQ * BA * G4];
__device__ __align__(16) __half g_Hh[2][BA * HD];          // h exchange fp16
__device__ unsigned g_cnt[8];

// ---------------- helpers ----------------
__device__ __forceinline__ uint32_t smem_u32(const void* p) {
    uint32_t a;
    asm("{ .reg .u64 t; cvta.to.shared.u64 t, %1; cvt.u32.u64 %0, t; }" : "=r"(a) : "l"(p));
    return a;
}
__device__ __forceinline__ void ldsm4(uint32_t* r, uint32_t a) {
    asm volatile("ldmatrix.sync.aligned.m8n8.x4.shared.b16 {%0,%1,%2,%3}, [%4];"
                 : "=r"(r[0]), "=r"(r[1]), "=r"(r[2]), "=r"(r[3]) : "r"(a));
}
__device__ __forceinline__ void ldsm2(uint32_t* r, uint32_t a) {
    asm volatile("ldmatrix.sync.aligned.m8n8.x2.shared.b16 {%0,%1}, [%2];"
                 : "=r"(r[0]), "=r"(r[1]) : "r"(a));
}
__device__ __forceinline__ void mma16816h(float* d, const uint32_t* a, const uint32_t* b) {
    asm volatile("mma.sync.aligned.m16n8k16.row.col.f32.f16.f16.f32 "
                 "{%0,%1,%2,%3}, {%4,%5,%6,%7}, {%8,%9}, {%0,%1,%2,%3};"
                 : "+f"(d[0]), "+f"(d[1]), "+f"(d[2]), "+f"(d[3])
                 : "r"(a[0]), "r"(a[1]), "r"(a[2]), "r"(a[3]), "r"(b[0]), "r"(b[1]));
}
__device__ __forceinline__ void st_cg_u16h(__half* p, __half v) {
    unsigned short us;
    memcpy(&us, &v, 2);
    asm volatile("st.global.cg.u16 [%0], %1;" :: "l"(p), "h"(us) : "memory");
}

// ---------------- prep ----------------
__global__ void prep_kernel(
    const float* Wxi, const float* bxi, const float* Whi, const float* bhi,
    const float* Wxf, const float* bxf, const float* Whf, const float* bhf,
    const float* Wxo, const float* bxo, const float* Who, const float* bho,
    const float* Wxc, const float* bxc, const float* Whc, const float* bhc)
{
    const float* Wx[4] = {Wxi, Wxf, Wxo, Wxc};
    const float* bx[4] = {bxi, bxf, bxo, bxc};
    const float* Wh[4] = {Whi, Whf, Who, Whc};
    const float* bh[4] = {bhi, bhf, bho, bhc};
    long idx = (long)blockIdx.x * 256 + threadIdx.x;

    if (idx < 524288L) {                       // WX fp16, [n][i]
        int i = (int)(idx & 255), n = (int)(idx >> 8);
        int g = n >> 9, j = n & 511;
        g_WXh[idx] = __float2half_rn(Wx[g][(size_t)j * IN + i]);
        return;
    }
    idx -= 524288L;
    if (idx < 2048L) {
        int g = (int)(idx >> 9), j = (int)(idx & 511);
        g_BIAS[idx] = bx[g][j] + bh[g][j];
        return;
    }
    idx -= 2048L;
    if (idx < 1048576L) {                      // WH fp16
        int k = (int)(idx & 511);
        int r = (int)((idx >> 9) & 63);
        int hg = (int)(idx >> 15);
        int g = r >> 4, j = hg * 16 + (r & 15);
        g_WHh[idx] = __float2half_rn(Wh[g][(size_t)j * HD + k]);
        return;
    }
    idx -= 1048576L;
    if (idx < 32768L) {
        g_Hh[1][idx] = __float2half_rn(0.f);
        return;
    }
    idx -= 32768L;
    if (idx < 8L) g_cnt[idx] = 0u;
}

// ---------------- x -> fp16, layout [(s<<6)|b][i] ----------------
__global__ __launch_bounds__(256) void xsplit_kernel(const float* __restrict__ x)
{
    long idx = (long)blockIdx.x * 256 + threadIdx.x;
    long e = idx * 4;
    int i = (int)(e & 255);
    int s = (int)((e >> 8) & 1023);
    int b = (int)(e >> 18);
    float4 v = __ldg((const float4*)(x + e));
    __half h[4] = {__float2half_rn(v.x), __float2half_rn(v.y),
                   __float2half_rn(v.z), __float2half_rn(v.w)};
    size_t off = (((size_t)((s << 6) | b)) << 8) + i;
    *(uint2*)(g_Xh + off) = *(uint2*)h;
}

// ---------------- xproj: single-term fp16 HMMA (proven R10) ----------------
#define XPAD 136
#define XS_A 0
#define XS_B (128 * XPAD * 2)
#define XSMEM_BYTES (2 * 128 * XPAD * 2)

__global__ __launch_bounds__(256, 1) void xproj_hmma_kernel()
{
    extern __shared__ char sm[];
    int tid = threadIdx.x;
    int wid = tid >> 5, lane = tid & 31;
    int n0 = blockIdx.x * 128, m0 = blockIdx.y * 128;
    int mh = wid & 1, nh = wid >> 1;

    uint32_t smb = smem_u32(sm);
    int arow = lane & 15, ak = (lane >= 16) ? 8 : 0;
    uint32_t aB = smb + XS_A + ((mh * 64 + arow) * XPAD + ak) * 2;
    int brow = lane & 7, bk = (lane & 8) ? 8 : 0;
    uint32_t bB = smb + XS_B + ((nh * 32 + brow) * XPAD + bk) * 2;

    float d[4][4][4];
#pragma unroll
    for (int mi = 0; mi < 4; mi++)
#pragma unroll
        for (int ni = 0; ni < 4; ni++)
#pragma unroll
            for (int q = 0; q < 4; q++) d[mi][ni][q] = 0.f;

    int fr = tid >> 1, fh = (tid & 1) * 64;
#pragma unroll
    for (int kc = 0; kc < 2; kc++) {
        int k0 = kc * 128;
        {
            const uint4* sa = (const uint4*)(g_Xh + (((size_t)(m0 + fr)) << 8) + k0 + fh);
            const uint4* sb = (const uint4*)(g_WXh + (((size_t)(n0 + fr)) << 8) + k0 + fh);
            uint4* da4 = (uint4*)(sm + XS_A + (fr * XPAD + fh) * 2);
            uint4* db4 = (uint4*)(sm + XS_B + (fr * XPAD + fh) * 2);
#pragma unroll
            for (int c = 0; c < 8; c++) {
                da4[c] = __ldg(sa + c);
                db4[c] = __ldg(sb + c);
            }
        }
        __syncthreads();
#pragma unroll
        for (int ks = 0; ks < 8; ks++) {
            uint32_t ko = (uint32_t)ks * 32;
            uint32_t ah[4][4], bh[4][2];
#pragma unroll
            for (int mi = 0; mi < 4; mi++)
                ldsm4(ah[mi], aB + mi * (16 * XPAD * 2) + ko);
#pragma unroll
            for (int ni = 0; ni < 4; ni++)
                ldsm2(bh[ni], bB + ni * (8 * XPAD * 2) + ko);
#pragma unroll
            for (int mi = 0; mi < 4; mi++)
#pragma unroll
                for (int ni = 0; ni < 4; ni++)
                    mma16816h(d[mi][ni], ah[mi], bh[ni]);
        }
        __syncthreads();
    }

    int row_l = lane >> 2, col_l = (lane & 3) * 2;
#pragma unroll
    for (int mi = 0; mi < 4; mi++)
#pragma unroll
        for (int ni = 0; ni < 4; ni++) {
            int gr = m0 + mh * 64 + mi * 16 + row_l;
            int gc = n0 + nh * 32 + ni * 8 + col_l;
            float2 bb = *(const float2*)(g_BIAS + gc);
            float* o = g_XG + (size_t)gr * G4 + gc;
            *(float2*)o = make_float2(d[mi][ni][0] + bb.x, d[mi][ni][1] + bb.y);
            *(float2*)(o + 8 * G4) = make_float2(d[mi][ni][2] + bb.x, d[mi][ni][3] + bb.y);
        }
}

// ---------------- lstm: A-in-regs + R10-proven sync skeleton ----------------
// 128 CTAs = 4 bg x 32 hg; 512 thr = 16 warps = 4 mw x 4 kh.
// SMEM: W staged at [0,64*WPAD*2) during init only; steady state:
//   HH [16][WPAD] fp16 at 0, Cred [4][64*17] f32 at OFF_CRED.
#define OFF_CRED (16 * WPAD * 2 + 64)
#define LSMEM_BYTES (64 * WPAD * 2)

__global__ __launch_bounds__(512, 1) void lstm_hmma_kernel(float* __restrict__ out)
{
    extern __shared__ char sm[];
    int tid = threadIdx.x;
    int wid = tid >> 5, lane = tid & 31;
    int bg = blockIdx.x >> 5;
    int hg = blockIdx.x & 31;
    int mw = wid & 3;            // M quarter (16 rows)
    int kh = wid >> 2;           // K quarter (128 k)

    {   // stage W [64][WPAD]
        int r = tid >> 3, part = tid & 7;
        const uint4* s4 = (const uint4*)(g_WHh + ((size_t)(hg * 64 + r) << 9) + part * 64);
        uint4* d4 = (uint4*)(sm + (r * WPAD + part * 64) * 2);
#pragma unroll
        for (int i = 0; i < 8; i++) d4[i] = s4[i];
    }
    __syncthreads();

    uint32_t smb = smem_u32(sm);
    uint32_t areg[8][4];
    {   // A frags -> registers (once)
        int arow = lane & 15, ako = (lane >= 16) ? 8 : 0;
        uint32_t aB = smb + ((mw * 16 + arow) * WPAD + kh * 128 + ako) * 2;
#pragma unroll
        for (int kt = 0; kt < 8; kt++) ldsm4(areg[kt], aB + kt * 32);
    }
    __syncthreads();   // staging region now reused as HH + Cred

    int brow = (lane & 7) | ((lane & 16) >> 1);
    int bko = (lane & 8) ? 8 : 0;
    uint32_t bB = smb + (brow * WPAD + kh * 128 + bko) * 2;

    float* Cred = (float*)(sm + OFF_CRED);     // [4][64*17]
    float* Credk = Cred + kh * (64 * 17);
    int drow = mw * 16 + (lane >> 2), dcol = (lane & 3) * 2;

    int jl = tid & 15, b = (tid >> 4) & 15;
    int hwr = (bg * 16 + b) * HD + hg * 16 + jl;
    float c_reg = 0.f;

    long fuse = 50000000L;   // kernel-lifetime spin budget

    for (int s = 0; s < SQ; s++) {
        float xgi, xgf, xgo, xgc;
        if (tid < 256) {   // xg prefetch, hidden behind wait
            const float* xgr = g_XG + (((size_t)(s * 64 + bg * 16 + b)) << 11) + hg * 16 + jl;
            xgi = __ldg(xgr);
            xgf = __ldg(xgr + 512);
            xgo = __ldg(xgr + 1024);
            xgc = __ldg(xgr + 1536);
        }
        if (s > 0 && tid == 0) {   // R10-proven: tid0 waits on the bg counter
            unsigned tgt = 32u * (unsigned)s;
            unsigned v;
            do {
                asm volatile("ld.acquire.gpu.global.u32 %0, [%1];"
                             : "=r"(v) : "l"(&g_cnt[bg]) : "memory");
            } while (v < tgt && --fuse > 0);
        }
        __syncthreads();

        {   // h_{s-1} fp16 -> SMEM [16][WPAD]; 512 threads x 32B
            int row = tid >> 5, ch = (tid & 31) * 16;
            const uint4* srcv = (const uint4*)(g_Hh[(s + 1) & 1] + (size_t)(bg * 16 + row) * HD + ch);
            uint4* dst = (uint4*)(sm + (row * WPAD + ch) * 2);
            dst[0] = __ldcg(srcv);
            dst[1] = __ldcg(srcv + 1);
        }
        __syncthreads();

        float c0[4] = {0, 0, 0, 0}, c1[4] = {0, 0, 0, 0};
#pragma unroll
        for (int kt = 0; kt < 8; kt++) {
            uint32_t bf[4];
            ldsm4(bf, bB + kt * 32);
            mma16816h(c0, areg[kt], bf);
            mma16816h(c1, areg[kt], bf + 2);
        }
        Credk[drow * 17 + dcol]            = c0[0];
        Credk[drow * 17 + dcol + 1]        = c0[1];
        Credk[(drow + 8) * 17 + dcol]      = c0[2];
        Credk[(drow + 8) * 17 + dcol + 1]  = c0[3];
        Credk[drow * 17 + dcol + 8]        = c1[0];
        Credk[drow * 17 + dcol + 9]        = c1[1];
        Credk[(drow + 8) * 17 + dcol + 8]  = c1[2];
        Credk[(drow + 8) * 17 + dcol + 9]  = c1[3];
        __syncthreads();

        if (tid < 256) {
            float gi = xgi, gf = xgf, go = xgo, gc = xgc;
#pragma unroll
            for (int q = 0; q < 4; q++) {
                const float* cp = Cred + q * (64 * 17);
                gi += cp[jl * 17 + b];
                gf += cp[(16 + jl) * 17 + b];
                go += cp[(32 + jl) * 17 + b];
                gc += cp[(48 + jl) * 17 + b];
            }
            float iv = 1.f / (1.f + __expf(-gi));
            float fv = 1.f / (1.f + __expf(-gf));
            float ov = 1.f / (1.f + __expf(-go));
            float gv = tanhf(gc);
            c_reg = fv * c_reg + iv * gv;
            float hv = ov * tanhf(c_reg);
            st_cg_u16h(g_Hh[s & 1] + hwr, __float2half_rn(hv));
            if (s == SQ - 1) {
                out[hwr]         = hv;
                out[32768 + hwr] = c_reg;
            }
        }
        __syncthreads();   // pointwise reads done before next-step Cred/HH writes
        if (tid == 0)
            asm volatile("red.release.gpu.global.add.u32 [%0], %1;"
                         :: "l"(&g_cnt[bg]), "r"(1u) : "memory");
    }
}

// ---------------- launch ----------------
extern "C" void kernel_launch(void* const* d_in, const int* in_sizes, int n_in,
                              void* d_out, int out_size)
{
    const float* x = (const float*)d_in[0];
    cudaFuncSetAttribute(lstm_hmma_kernel, cudaFuncAttributeMaxDynamicSharedMemorySize, LSMEM_BYTES);
    cudaFuncSetAttribute(xproj_hmma_kernel, cudaFuncAttributeMaxDynamicSharedMemorySize, XSMEM_BYTES);

    prep_kernel<<<6281, 256>>>(
        (const float*)d_in[1],  (const float*)d_in[2],  (const float*)d_in[3],  (const float*)d_in[4],
        (const float*)d_in[5],  (const float*)d_in[6],  (const float*)d_in[7],  (const float*)d_in[8],
        (const float*)d_in[9],  (const float*)d_in[10], (const float*)d_in[11], (const float*)d_in[12],
        (const float*)d_in[13], (const float*)d_in[14], (const float*)d_in[15], (const float*)d_in[16]);

    xsplit_kernel<<<16384, 256>>>(x);

    dim3 g1(16, 512);
    xproj_hmma_kernel<<<g1, 256, XSMEM_BYTES>>>();

    lstm_hmma_kernel<<<128, 512, LSMEM_BYTES>>>((float*)d_out);
}

// round 15
// speedup vs baseline: 2.8483x; 1.0169x over previous
#include <cuda_runtime.h>
#include <cuda_fp16.h>
#include <cstdint>
#include <cstring>

#define SQ 1024
#define BA 64
#define IN 256
#define HD 512
#define G4 2048
#define WPAD 520

// ---------------- device scratch ----------------
__device__ __align__(16) float g_BIAS[G4];
__device__ __align__(16) __half g_WXh[G4 * IN];            // [n][i] fp16
__device__ __align__(16) __half g_Xh[(size_t)65536 * IN];  // [m=(s<<6)|b][i] fp16
__device__ __align__(16) __half g_WHh[32 * 64 * 512];      // [hg][row=g*16+jl][k] fp16
__device__ __align__(16) float g_XG[(size_t)SQ * BA * G4];
__device__ __align__(16) __half g_Hh[2][BA * HD];          // h exchange fp16
__device__ unsigned g_cnt[128];                            // counter bg at [bg*32] (line-padded)

// ---------------- helpers ----------------
__device__ __forceinline__ uint32_t smem_u32(const void* p) {
    uint32_t a;
    asm("{ .reg .u64 t; cvta.to.shared.u64 t, %1; cvt.u32.u64 %0, t; }" : "=r"(a) : "l"(p));
    return a;
}
__device__ __forceinline__ void ldsm4(uint32_t* r, uint32_t a) {
    asm volatile("ldmatrix.sync.aligned.m8n8.x4.shared.b16 {%0,%1,%2,%3}, [%4];"
                 : "=r"(r[0]), "=r"(r[1]), "=r"(r[2]), "=r"(r[3]) : "r"(a));
}
__device__ __forceinline__ void ldsm2(uint32_t* r, uint32_t a) {
    asm volatile("ldmatrix.sync.aligned.m8n8.x2.shared.b16 {%0,%1}, [%2];"
                 : "=r"(r[0]), "=r"(r[1]) : "r"(a));
}
__device__ __forceinline__ void mma16816h(float* d, const uint32_t* a, const uint32_t* b) {
    asm volatile("mma.sync.aligned.m16n8k16.row.col.f32.f16.f16.f32 "
                 "{%0,%1,%2,%3}, {%4,%5,%6,%7}, {%8,%9}, {%0,%1,%2,%3};"
                 : "+f"(d[0]), "+f"(d[1]), "+f"(d[2]), "+f"(d[3])
                 : "r"(a[0]), "r"(a[1]), "r"(a[2]), "r"(a[3]), "r"(b[0]), "r"(b[1]));
}
__device__ __forceinline__ void st_cg_u16h(__half* p, __half v) {
    unsigned short us;
    memcpy(&us, &v, 2);
    asm volatile("st.global.cg.u16 [%0], %1;" :: "l"(p), "h"(us) : "memory");
}
__device__ __forceinline__ float tanh_fast(float x) {
    float t = __expf(2.f * x);
    return __fdividef(t - 1.f, t + 1.f);
}

// ---------------- prep ----------------
__global__ void prep_kernel(
    const float* Wxi, const float* bxi, const float* Whi, const float* bhi,
    const float* Wxf, const float* bxf, const float* Whf, const float* bhf,
    const float* Wxo, const float* bxo, const float* Who, const float* bho,
    const float* Wxc, const float* bxc, const float* Whc, const float* bhc)
{
    const float* Wx[4] = {Wxi, Wxf, Wxo, Wxc};
    const float* bx[4] = {bxi, bxf, bxo, bxc};
    const float* Wh[4] = {Whi, Whf, Who, Whc};
    const float* bh[4] = {bhi, bhf, bho, bhc};
    long idx = (long)blockIdx.x * 256 + threadIdx.x;

    if (idx < 524288L) {                       // WX fp16, [n][i]
        int i = (int)(idx & 255), n = (int)(idx >> 8);
        int g = n >> 9, j = n & 511;
        g_WXh[idx] = __float2half_rn(Wx[g][(size_t)j * IN + i]);
        return;
    }
    idx -= 524288L;
    if (idx < 2048L) {
        int g = (int)(idx >> 9), j = (int)(idx & 511);
        g_BIAS[idx] = bx[g][j] + bh[g][j];
        return;
    }
    idx -= 2048L;
    if (idx < 1048576L) {                      // WH fp16
        int k = (int)(idx & 511);
        int r = (int)((idx >> 9) & 63);
        int hg = (int)(idx >> 15);
        int g = r >> 4, j = hg * 16 + (r & 15);
        g_WHh[idx] = __float2half_rn(Wh[g][(size_t)j * HD + k]);
        return;
    }
    idx -= 1048576L;
    if (idx < 32768L) {
        g_Hh[1][idx] = __float2half_rn(0.f);
        return;
    }
    idx -= 32768L;
    if (idx < 128L) g_cnt[idx] = 0u;
}

// ---------------- x -> fp16, layout [(s<<6)|b][i] ----------------
__global__ __launch_bounds__(256) void xsplit_kernel(const float* __restrict__ x)
{
    long idx = (long)blockIdx.x * 256 + threadIdx.x;
    long e = idx * 4;
    int i = (int)(e & 255);
    int s = (int)((e >> 8) & 1023);
    int b = (int)(e >> 18);
    float4 v = __ldg((const float4*)(x + e));
    __half h[4] = {__float2half_rn(v.x), __float2half_rn(v.y),
                   __float2half_rn(v.z), __float2half_rn(v.w)};
    size_t off = (((size_t)((s << 6) | b)) << 8) + i;
    *(uint2*)(g_Xh + off) = *(uint2*)h;
}

// ---------------- xproj: single-term fp16 HMMA (proven R10) ----------------
#define XPAD 136
#define XS_A 0
#define XS_B (128 * XPAD * 2)
#define XSMEM_BYTES (2 * 128 * XPAD * 2)

__global__ __launch_bounds__(256, 1) void xproj_hmma_kernel()
{
    extern __shared__ char sm[];
    int tid = threadIdx.x;
    int wid = tid >> 5, lane = tid & 31;
    int n0 = blockIdx.x * 128, m0 = blockIdx.y * 128;
    int mh = wid & 1, nh = wid >> 1;

    uint32_t smb = smem_u32(sm);
    int arow = lane & 15, ak = (lane >= 16) ? 8 : 0;
    uint32_t aB = smb + XS_A + ((mh * 64 + arow) * XPAD + ak) * 2;
    int brow = lane & 7, bk = (lane & 8) ? 8 : 0;
    uint32_t bB = smb + XS_B + ((nh * 32 + brow) * XPAD + bk) * 2;

    float d[4][4][4];
#pragma unroll
    for (int mi = 0; mi < 4; mi++)
#pragma unroll
        for (int ni = 0; ni < 4; ni++)
#pragma unroll
            for (int q = 0; q < 4; q++) d[mi][ni][q] = 0.f;

    int fr = tid >> 1, fh = (tid & 1) * 64;
#pragma unroll
    for (int kc = 0; kc < 2; kc++) {
        int k0 = kc * 128;
        {
            const uint4* sa = (const uint4*)(g_Xh + (((size_t)(m0 + fr)) << 8) + k0 + fh);
            const uint4* sb = (const uint4*)(g_WXh + (((size_t)(n0 + fr)) << 8) + k0 + fh);
            uint4* da4 = (uint4*)(sm + XS_A + (fr * XPAD + fh) * 2);
            uint4* db4 = (uint4*)(sm + XS_B + (fr * XPAD + fh) * 2);
#pragma unroll
            for (int c = 0; c < 8; c++) {
                da4[c] = __ldg(sa + c);
                db4[c] = __ldg(sb + c);
            }
        }
        __syncthreads();
#pragma unroll
        for (int ks = 0; ks < 8; ks++) {
            uint32_t ko = (uint32_t)ks * 32;
            uint32_t ah[4][4], bh[4][2];
#pragma unroll
            for (int mi = 0; mi < 4; mi++)
                ldsm4(ah[mi], aB + mi * (16 * XPAD * 2) + ko);
#pragma unroll
            for (int ni = 0; ni < 4; ni++)
                ldsm2(bh[ni], bB + ni * (8 * XPAD * 2) + ko);
#pragma unroll
            for (int mi = 0; mi < 4; mi++)
#pragma unroll
                for (int ni = 0; ni < 4; ni++)
                    mma16816h(d[mi][ni], ah[mi], bh[ni]);
        }
        __syncthreads();
    }

    int row_l = lane >> 2, col_l = (lane & 3) * 2;
#pragma unroll
    for (int mi = 0; mi < 4; mi++)
#pragma unroll
        for (int ni = 0; ni < 4; ni++) {
            int gr = m0 + mh * 64 + mi * 16 + row_l;
            int gc = n0 + nh * 32 + ni * 8 + col_l;
            float2 bb = *(const float2*)(g_BIAS + gc);
            float* o = g_XG + (size_t)gr * G4 + gc;
            *(float2*)o = make_float2(d[mi][ni][0] + bb.x, d[mi][ni][1] + bb.y);
            *(float2*)(o + 8 * G4) = make_float2(d[mi][ni][2] + bb.x, d[mi][ni][3] + bb.y);
        }
}

// ---------------- lstm: A-in-regs, tid0 poll, last-warp early signal ----------------
// 128 CTAs = 4 bg x 32 hg; 512 thr = 16 warps = 4 mw x 4 kh (R13 MMA mapping).
// Barriers/step: A(post-poll) B(post-fill) C(post-Cred). Final barrier replaced by
// smem token: last pointwise warp issues the CTA's single global signal.
#define OFF_CRED (16 * WPAD * 2 + 64)
#define OFF_SCNT (OFF_CRED + 4 * 64 * 17 * 4)
#define LSMEM_BYTES (64 * WPAD * 2)

__global__ __launch_bounds__(512, 1) void lstm_hmma_kernel(float* __restrict__ out)
{
    extern __shared__ char sm[];
    int tid = threadIdx.x;
    int wid = tid >> 5, lane = tid & 31;
    int bg = blockIdx.x >> 5;
    int hg = blockIdx.x & 31;
    int mw = wid & 3;            // M quarter (16 rows)
    int kh = wid >> 2;           // K quarter (128 k)

    {   // stage W [64][WPAD]
        int r = tid >> 3, part = tid & 7;
        const uint4* s4 = (const uint4*)(g_WHh + ((size_t)(hg * 64 + r) << 9) + part * 64);
        uint4* d4 = (uint4*)(sm + (r * WPAD + part * 64) * 2);
#pragma unroll
        for (int i = 0; i < 8; i++) d4[i] = s4[i];
    }
    __syncthreads();

    uint32_t smb = smem_u32(sm);
    uint32_t areg[8][4];
    {   // A frags -> registers (once)
        int arow = lane & 15, ako = (lane >= 16) ? 8 : 0;
        uint32_t aB = smb + ((mw * 16 + arow) * WPAD + kh * 128 + ako) * 2;
#pragma unroll
        for (int kt = 0; kt < 8; kt++) ldsm4(areg[kt], aB + kt * 32);
    }
    __syncthreads();   // staging region now reused as HH + Cred

    uint32_t scnt = smb + OFF_SCNT;
    if (tid == 0)
        asm volatile("st.shared.u32 [%0], %1;" :: "r"(scnt), "r"(0u) : "memory");

    int brow = (lane & 7) | ((lane & 16) >> 1);
    int bko = (lane & 8) ? 8 : 0;
    uint32_t bB = smb + (brow * WPAD + kh * 128 + bko) * 2;

    float* Cred = (float*)(sm + OFF_CRED);     // [4][64*17]
    float* Credk = Cred + kh * (64 * 17);
    int drow = mw * 16 + (lane >> 2), dcol = (lane & 3) * 2;

    int jl = tid & 15, b = (tid >> 4) & 15;
    int hwr = (bg * 16 + b) * HD + hg * 16 + jl;
    float c_reg = 0.f;

    unsigned* cntp = &g_cnt[bg * 32];
    long fuse = 50000000L;   // kernel-lifetime spin budget

    for (int s = 0; s < SQ; s++) {
        float xgi, xgf, xgo, xgc;
        if (tid < 256) {   // xg prefetch, hidden behind wait
            const float* xgr = g_XG + (((size_t)(s * 64 + bg * 16 + b)) << 11) + hg * 16 + jl;
            xgi = __ldg(xgr);
            xgf = __ldg(xgr + 512);
            xgo = __ldg(xgr + 1024);
            xgc = __ldg(xgr + 1536);
        }
        if (s > 0 && tid == 0) {   // R13-proven: single poller per CTA
            unsigned tgt = 32u * (unsigned)s;
            unsigned v;
            do {
                asm volatile("ld.acquire.gpu.global.u32 %0, [%1];"
                             : "=r"(v) : "l"(cntp) : "memory");
            } while (v < tgt && --fuse > 0);
        }
        __syncthreads();   // A

        {   // h_{s-1} fp16 -> SMEM [16][WPAD]; 512 threads x 32B
            int row = tid >> 5, ch = (tid & 31) * 16;
            const uint4* srcv = (const uint4*)(g_Hh[(s + 1) & 1] + (size_t)(bg * 16 + row) * HD + ch);
            uint4* dst = (uint4*)(sm + (row * WPAD + ch) * 2);
            dst[0] = __ldcg(srcv);
            dst[1] = __ldcg(srcv + 1);
        }
        __syncthreads();   // B

        float c0[4] = {0, 0, 0, 0}, c1[4] = {0, 0, 0, 0};
#pragma unroll
        for (int kt = 0; kt < 8; kt++) {
            uint32_t bf[4];
            ldsm4(bf, bB + kt * 32);
            mma16816h(c0, areg[kt], bf);
            mma16816h(c1, areg[kt], bf + 2);
        }
        Credk[drow * 17 + dcol]            = c0[0];
        Credk[drow * 17 + dcol + 1]        = c0[1];
        Credk[(drow + 8) * 17 + dcol]      = c0[2];
        Credk[(drow + 8) * 17 + dcol + 1]  = c0[3];
        Credk[drow * 17 + dcol + 8]        = c1[0];
        Credk[drow * 17 + dcol + 9]        = c1[1];
        Credk[(drow + 8) * 17 + dcol + 8]  = c1[2];
        Credk[(drow + 8) * 17 + dcol + 9]  = c1[3];
        __syncthreads();   // C

        if (tid < 256) {
            float gi = xgi, gf = xgf, go = xgo, gc = xgc;
#pragma unroll
            for (int q = 0; q < 4; q++) {
                const float* cp = Cred + q * (64 * 17);
                gi += cp[jl * 17 + b];
                gf += cp[(16 + jl) * 17 + b];
                go += cp[(32 + jl) * 17 + b];
                gc += cp[(48 + jl) * 17 + b];
            }
            float iv = 1.f / (1.f + __expf(-gi));
            float fv = 1.f / (1.f + __expf(-gf));
            float ov = 1.f / (1.f + __expf(-go));
            float gv = tanh_fast(gc);
            c_reg = fv * c_reg + iv * gv;
            float hv = ov * tanh_fast(c_reg);
            st_cg_u16h(g_Hh[s & 1] + hwr, __float2half_rn(hv));
            if (s == SQ - 1) {
                out[hwr]         = hv;
                out[32768 + hwr] = c_reg;
            }
            __syncwarp();                      // warp's 32 h stores done (warp fence)
            if (lane == 0) {
                unsigned old;
                asm volatile("atom.acq_rel.cta.shared.add.u32 %0, [%1], %2;"
                             : "=r"(old) : "r"(scnt), "r"(1u) : "memory");
                if (old == 7u) {               // last pointwise warp of this CTA
                    asm volatile("st.shared.u32 [%0], %1;" :: "r"(scnt), "r"(0u) : "memory");
                    asm volatile("red.release.gpu.global.add.u32 [%0], %1;"
                                 :: "l"(cntp), "r"(1u) : "memory");
                }
            }
        }
        // no final CTA barrier: HH WAR closed by C(s)->A(s+1); Cred WAR closed by
        // pointwise-before-A(s+1) + B(s+1); scnt reset ordered by A(s+1).
    }
}

// ---------------- launch ----------------
extern "C" void kernel_launch(void* const* d_in, const int* in_sizes, int n_in,
                              void* d_out, int out_size)
{
    const float* x = (const float*)d_in[0];
    cudaFuncSetAttribute(lstm_hmma_kernel, cudaFuncAttributeMaxDynamicSharedMemorySize, LSMEM_BYTES);
    cudaFuncSetAttribute(xproj_hmma_kernel, cudaFuncAttributeMaxDynamicSharedMemorySize, XSMEM_BYTES);

    prep_kernel<<<6281, 256>>>(
        (const float*)d_in[1],  (const float*)d_in[2],  (const float*)d_in[3],  (const float*)d_in[4],
        (const float*)d_in[5],  (const float*)d_in[6],  (const float*)d_in[7],  (const float*)d_in[8],
        (const float*)d_in[9],  (const float*)d_in[10], (const float*)d_in[11], (const float*)d_in[12],
        (const float*)d_in[13], (const float*)d_in[14], (const float*)d_in[15], (const float*)d_in[16]);

    xsplit_kernel<<<16384, 256>>>(x);

    dim3 g1(16, 512);
    xproj_hmma_kernel<<<g1, 256, XSMEM_BYTES>>>();

    lstm_hmma_kernel<<<128, 512, LSMEM_BYTES>>>((float*)d_out);
}